// round 1
// baseline (speedup 1.0000x reference)
#include <cuda_runtime.h>

// Problem constants
#define Bb   2
#define Ss   2048
#define Hh   2048
#define NHh  16
#define HDd  128
#define Mm   4096   // B*S

// Scratch: Q,K,V in head-major [B, NH, S, HD]; AO in [B, S, H]
__device__ float g_Q[(size_t)Mm * Hh];
__device__ float g_K[(size_t)Mm * Hh];
__device__ float g_V[(size_t)Mm * Hh];
__device__ float g_AO[(size_t)Mm * Hh];

// ---------------------------------------------------------------------------
// SGEMM: C[M,N] = A[M,K] @ B[K,N] + bias[N]
// 128x128 block tile, BK=8, 256 threads, 8x8 per thread.
// HEADMAJOR: scatter output to [B, NH, S, HD] layout.
// ---------------------------------------------------------------------------
template <bool HEADMAJOR>
__global__ __launch_bounds__(256) void sgemm_bias(
    const float* __restrict__ A, const float* __restrict__ Bw,
    const float* __restrict__ bias, float* __restrict__ C,
    int M, int N, int K)
{
    __shared__ float As[8][128];
    __shared__ float Bs[8][128];

    const int tid = threadIdx.x;
    const int bm = blockIdx.y * 128;
    const int bn = blockIdx.x * 128;

    const int arow = tid >> 1;          // 0..127
    const int acol = (tid & 1) * 4;     // 0 or 4
    const int brow = tid >> 5;          // 0..7
    const int bcol = (tid & 31) * 4;    // 0..124

    const int tr = (tid >> 4) * 8;      // thread row base in tile
    const int tc = (tid & 15) * 8;      // thread col base in tile

    float acc[8][8];
#pragma unroll
    for (int i = 0; i < 8; i++)
#pragma unroll
        for (int j = 0; j < 8; j++) acc[i][j] = 0.f;

    const float* Aptr = A + (size_t)(bm + arow) * K + acol;
    const float* Bptr = Bw + (size_t)brow * N + bn + bcol;

    for (int k0 = 0; k0 < K; k0 += 8) {
        float4 av = *(const float4*)(Aptr + k0);
        As[acol + 0][arow] = av.x;
        As[acol + 1][arow] = av.y;
        As[acol + 2][arow] = av.z;
        As[acol + 3][arow] = av.w;
        *(float4*)(&Bs[brow][bcol]) = *(const float4*)(Bptr + (size_t)k0 * N);
        __syncthreads();

#pragma unroll
        for (int kk = 0; kk < 8; kk++) {
            float4 a0 = *(const float4*)&As[kk][tr];
            float4 a1 = *(const float4*)&As[kk][tr + 4];
            float4 b0 = *(const float4*)&Bs[kk][tc];
            float4 b1 = *(const float4*)&Bs[kk][tc + 4];
            float a[8] = {a0.x, a0.y, a0.z, a0.w, a1.x, a1.y, a1.z, a1.w};
            float b[8] = {b0.x, b0.y, b0.z, b0.w, b1.x, b1.y, b1.z, b1.w};
#pragma unroll
            for (int i = 0; i < 8; i++)
#pragma unroll
                for (int j = 0; j < 8; j++)
                    acc[i][j] = fmaf(a[i], b[j], acc[i][j]);
        }
        __syncthreads();
    }

#pragma unroll
    for (int i = 0; i < 8; i++) {
        const int m = bm + tr + i;
#pragma unroll
        for (int j = 0; j < 8; j++) {
            const int n = bn + tc + j;
            float v = acc[i][j] + bias[n];
            if (HEADMAJOR) {
                const int bb = m >> 11;          // m / S
                const int ss = m & (Ss - 1);
                const int hh = n >> 7;           // n / HD
                const int dd = n & (HDd - 1);
                C[(((size_t)(bb * NHh + hh) * Ss) + ss) * HDd + dd] = v;
            } else {
                C[(size_t)m * N + n] = v;
            }
        }
    }
}

// ---------------------------------------------------------------------------
// Flash-style causal attention.
// One CTA = one (b, h, 64-query tile). 256 threads.
// Streams 64-key tiles with online softmax; O accumulators in registers.
// ---------------------------------------------------------------------------
#define QT 64
#define KT 64
#define LDK 132   // padded K/V row (floats) to dodge bank conflicts
#define LDP 65    // padded P row

// smem floats: Q 64*128 + K 64*132 + V 64*132 + P 64*65 + 3*64
#define ATT_SMEM_FLOATS (QT * HDd + KT * LDK * 2 + QT * LDP + 3 * QT)
#define ATT_SMEM_BYTES (ATT_SMEM_FLOATS * 4)

__global__ __launch_bounds__(256) void attn_kernel(
    const float* __restrict__ gQ, const float* __restrict__ gK,
    const float* __restrict__ gV, float* __restrict__ gAO)
{
    extern __shared__ float sm[];
    float* Qs  = sm;
    float* Ks  = Qs + QT * HDd;
    float* Vs  = Ks + KT * LDK;
    float* Ps  = Vs + KT * LDK;
    float* m_s = Ps + QT * LDP;
    float* l_s = m_s + QT;
    float* al_s = l_s + QT;

    const int qt = blockIdx.x;
    const int h  = blockIdx.y;
    const int b  = blockIdx.z;
    const int tid = threadIdx.x;
    const float scale = 0.08838834764831845f;  // 128^-0.5

    const size_t base = ((size_t)(b * NHh + h)) * Ss * HDd;
    const float* qp = gQ + base + (size_t)qt * QT * HDd;

    // Load Q tile, pre-scaled
    for (int idx = tid; idx < QT * HDd / 4; idx += 256) {
        float4 v = ((const float4*)qp)[idx];
        v.x *= scale; v.y *= scale; v.z *= scale; v.w *= scale;
        ((float4*)Qs)[idx] = v;
    }
    if (tid < QT) { m_s[tid] = -1e30f; l_s[tid] = 0.f; }

    float o[4][8];
#pragma unroll
    for (int i = 0; i < 4; i++)
#pragma unroll
        for (int j = 0; j < 8; j++) o[i][j] = 0.f;

    const int sy = (tid >> 4) * 4;   // q rows (both score & PV phases)
    const int sx = (tid & 15) * 4;   // k cols (score phase)
    const int rd = (tid & 15) * 8;   // d cols (PV phase)
    __syncthreads();

    for (int kt = 0; kt <= qt; kt++) {
        const float* kp = gK + base + (size_t)kt * KT * HDd;
        const float* vp = gV + base + (size_t)kt * KT * HDd;
        for (int idx = tid; idx < KT * (HDd / 4); idx += 256) {
            const int r = idx >> 5;
            const int c = (idx & 31) * 4;
            *(float4*)&Ks[r * LDK + c] = ((const float4*)kp)[idx];
            *(float4*)&Vs[r * LDK + c] = ((const float4*)vp)[idx];
        }
        __syncthreads();

        // --- scores: 4x4 per thread, dot over HD=128 ---
        float s[4][4];
#pragma unroll
        for (int i = 0; i < 4; i++)
#pragma unroll
            for (int j = 0; j < 4; j++) s[i][j] = 0.f;

#pragma unroll 8
        for (int kk = 0; kk < HDd; kk += 4) {
            float qa[4][4], ka[4][4];
#pragma unroll
            for (int i = 0; i < 4; i++) {
                float4 t = *(const float4*)&Qs[(sy + i) * HDd + kk];
                qa[i][0] = t.x; qa[i][1] = t.y; qa[i][2] = t.z; qa[i][3] = t.w;
            }
#pragma unroll
            for (int j = 0; j < 4; j++) {
                float4 t = *(const float4*)&Ks[(sx + j) * LDK + kk];
                ka[j][0] = t.x; ka[j][1] = t.y; ka[j][2] = t.z; ka[j][3] = t.w;
            }
#pragma unroll
            for (int i = 0; i < 4; i++)
#pragma unroll
                for (int j = 0; j < 4; j++) {
                    s[i][j] = fmaf(qa[i][0], ka[j][0], s[i][j]);
                    s[i][j] = fmaf(qa[i][1], ka[j][1], s[i][j]);
                    s[i][j] = fmaf(qa[i][2], ka[j][2], s[i][j]);
                    s[i][j] = fmaf(qa[i][3], ka[j][3], s[i][j]);
                }
        }

        const bool diag = (kt == qt);
#pragma unroll
        for (int i = 0; i < 4; i++)
#pragma unroll
            for (int j = 0; j < 4; j++) {
                float v = s[i][j];
                if (diag && (sx + j) > (sy + i)) v = -1e30f;
                Ps[(sy + i) * LDP + sx + j] = v;
            }
        __syncthreads();

        // --- online softmax (row per thread, 64 rows) ---
        if (tid < QT) {
            const int r = tid;
            const float mo = m_s[r];
            float mx = mo;
            for (int c = 0; c < KT; c++) mx = fmaxf(mx, Ps[r * LDP + c]);
            const float al = __expf(mo - mx);
            float sum = 0.f;
            for (int c = 0; c < KT; c++) {
                float p = __expf(Ps[r * LDP + c] - mx);
                Ps[r * LDP + c] = p;
                sum += p;
            }
            m_s[r]  = mx;
            l_s[r]  = l_s[r] * al + sum;
            al_s[r] = al;
        }
        __syncthreads();

        // --- O rescale + P@V accumulate ---
        float al[4];
#pragma unroll
        for (int i = 0; i < 4; i++) al[i] = al_s[sy + i];
#pragma unroll
        for (int i = 0; i < 4; i++)
#pragma unroll
            for (int j = 0; j < 8; j++) o[i][j] *= al[i];

#pragma unroll 8
        for (int k = 0; k < KT; k++) {
            float p[4];
#pragma unroll
            for (int i = 0; i < 4; i++) p[i] = Ps[(sy + i) * LDP + k];
            float4 v0 = *(const float4*)&Vs[k * LDK + rd];
            float4 v1 = *(const float4*)&Vs[k * LDK + rd + 4];
            float vv[8] = {v0.x, v0.y, v0.z, v0.w, v1.x, v1.y, v1.z, v1.w};
#pragma unroll
            for (int i = 0; i < 4; i++)
#pragma unroll
                for (int j = 0; j < 8; j++)
                    o[i][j] = fmaf(p[i], vv[j], o[i][j]);
        }
        __syncthreads();
    }

    // --- write out: [B, S, H] row-major ---
    const int qrow = qt * QT;
#pragma unroll
    for (int i = 0; i < 4; i++) {
        const float inv = 1.f / l_s[sy + i];
        const size_t off =
            ((size_t)(b * Ss) + qrow + sy + i) * Hh + h * HDd + rd;
        float4 w0, w1;
        w0.x = o[i][0] * inv; w0.y = o[i][1] * inv;
        w0.z = o[i][2] * inv; w0.w = o[i][3] * inv;
        w1.x = o[i][4] * inv; w1.y = o[i][5] * inv;
        w1.z = o[i][6] * inv; w1.w = o[i][7] * inv;
        *(float4*)&gAO[off]     = w0;
        *(float4*)&gAO[off + 4] = w1;
    }
}

// ---------------------------------------------------------------------------
extern "C" void kernel_launch(void* const* d_in, const int* in_sizes, int n_in,
                              void* d_out, int out_size)
{
    (void)in_sizes; (void)n_in; (void)out_size;
    const float* x  = (const float*)d_in[0];
    // d_in[1] = mask (exact additive causal) -> applied analytically
    const float* wq = (const float*)d_in[2];
    const float* bq = (const float*)d_in[3];
    const float* wk = (const float*)d_in[4];
    const float* bk = (const float*)d_in[5];
    const float* wv = (const float*)d_in[6];
    const float* bv = (const float*)d_in[7];
    const float* wo = (const float*)d_in[8];
    const float* bo = (const float*)d_in[9];
    float* out = (float*)d_out;

    float *qP, *kP, *vP, *aP;
    cudaGetSymbolAddress((void**)&qP, g_Q);
    cudaGetSymbolAddress((void**)&kP, g_K);
    cudaGetSymbolAddress((void**)&vP, g_V);
    cudaGetSymbolAddress((void**)&aP, g_AO);

    dim3 gg(Hh / 128, Mm / 128), tt(256);
    sgemm_bias<true><<<gg, tt>>>(x, wq, bq, qP, Mm, Hh, Hh);
    sgemm_bias<true><<<gg, tt>>>(x, wk, bk, kP, Mm, Hh, Hh);
    sgemm_bias<true><<<gg, tt>>>(x, wv, bv, vP, Mm, Hh, Hh);

    cudaFuncSetAttribute(attn_kernel,
                         cudaFuncAttributeMaxDynamicSharedMemorySize,
                         ATT_SMEM_BYTES);
    attn_kernel<<<dim3(Ss / QT, NHh, Bb), 256, ATT_SMEM_BYTES>>>(qP, kP, vP, aP);

    sgemm_bias<false><<<gg, tt>>>(aP, wo, bo, out, Mm, Hh, Hh);
}

// round 3
// speedup vs baseline: 1.5037x; 1.5037x over previous
#include <cuda_runtime.h>
#include <cuda_bf16.h>
#include <cstdint>

// Problem constants
#define Bb   2
#define Ss   2048
#define Hh   2048
#define NHh  16
#define HDd  128
#define Mm   4096   // B*S

// ---------------------------------------------------------------------------
// Scratch (device globals; no allocation allowed)
// ---------------------------------------------------------------------------
__device__ float g_Q[(size_t)Mm * Hh];
__device__ float g_K[(size_t)Mm * Hh];
__device__ float g_V[(size_t)Mm * Hh];
__device__ float g_AO[(size_t)Mm * Hh];

__device__ __nv_bfloat16 g_Xh[(size_t)Mm * Hh];
__device__ __nv_bfloat16 g_Xl[(size_t)Mm * Hh];
__device__ __nv_bfloat16 g_AOh[(size_t)Mm * Hh];
__device__ __nv_bfloat16 g_AOl[(size_t)Mm * Hh];
__device__ __nv_bfloat16 g_Wh[4][(size_t)Hh * Hh];
__device__ __nv_bfloat16 g_Wl[4][(size_t)Hh * Hh];

// ---------------------------------------------------------------------------
// PTX helpers (sm_80-level only: legal in compute_103 PTX)
// ---------------------------------------------------------------------------
__device__ __forceinline__ uint32_t smem_to_u32(const void* p) {
    uint32_t a;
    asm("{ .reg .u64 t; cvta.to.shared.u64 t, %1; cvt.u32.u64 %0, t; }"
        : "=r"(a) : "l"(p));
    return a;
}

__device__ __forceinline__ void cp16(uint32_t s, const void* g) {
    asm volatile("cp.async.cg.shared.global [%0], [%1], 16;" :: "r"(s), "l"(g));
}
#define CP_COMMIT() asm volatile("cp.async.commit_group;" ::: "memory")
#define CP_WAIT0()  asm volatile("cp.async.wait_group 0;" ::: "memory")

__device__ __forceinline__ void ldm_x4(uint32_t& r0, uint32_t& r1, uint32_t& r2,
                                       uint32_t& r3, uint32_t addr) {
    asm volatile("ldmatrix.sync.aligned.m8n8.x4.shared.b16 {%0,%1,%2,%3}, [%4];"
                 : "=r"(r0), "=r"(r1), "=r"(r2), "=r"(r3) : "r"(addr));
}
__device__ __forceinline__ void ldm_x2(uint32_t& r0, uint32_t& r1, uint32_t addr) {
    asm volatile("ldmatrix.sync.aligned.m8n8.x2.shared.b16 {%0,%1}, [%2];"
                 : "=r"(r0), "=r"(r1) : "r"(addr));
}
__device__ __forceinline__ void mma_bf16(float* c, const uint32_t* a, const uint32_t* b) {
    asm volatile("mma.sync.aligned.m16n8k16.row.col.f32.bf16.bf16.f32 "
                 "{%0,%1,%2,%3}, {%4,%5,%6,%7}, {%8,%9}, {%0,%1,%2,%3};"
                 : "+f"(c[0]), "+f"(c[1]), "+f"(c[2]), "+f"(c[3])
                 : "r"(a[0]), "r"(a[1]), "r"(a[2]), "r"(a[3]), "r"(b[0]), "r"(b[1]));
}

// ---------------------------------------------------------------------------
// Split conversion: fp32 -> (bf16 hi, bf16 lo)
// ---------------------------------------------------------------------------
__global__ void convert_split(const float2* __restrict__ X,
                              __nv_bfloat162* __restrict__ Xh,
                              __nv_bfloat162* __restrict__ Xl, int n2)
{
    int i = blockIdx.x * blockDim.x + threadIdx.x;
    if (i >= n2) return;
    float2 v = X[i];
    __nv_bfloat16 h0 = __float2bfloat16_rn(v.x);
    __nv_bfloat16 h1 = __float2bfloat16_rn(v.y);
    float r0 = v.x - __bfloat162float(h0);
    float r1 = v.y - __bfloat162float(h1);
    Xh[i] = __nv_bfloat162(h0, h1);
    Xl[i] = __nv_bfloat162(__float2bfloat16_rn(r0), __float2bfloat16_rn(r1));
}

// Transpose + split: W[K,N] fp32 -> WT[N,K] bf16 hi/lo  (K=N=2048)
__global__ void transpose_split(const float* __restrict__ W,
                                __nv_bfloat16* __restrict__ Th,
                                __nv_bfloat16* __restrict__ Tl)
{
    __shared__ float t[32][33];
    const int n0 = blockIdx.x * 32, k0 = blockIdx.y * 32;
    const int tx = threadIdx.x, ty = threadIdx.y;   // (32, 8)
#pragma unroll
    for (int i = 0; i < 4; i++)
        t[ty + 8 * i][tx] = W[(size_t)(k0 + ty + 8 * i) * Hh + n0 + tx];
    __syncthreads();
#pragma unroll
    for (int i = 0; i < 4; i++) {
        float v = t[tx][ty + 8 * i];
        __nv_bfloat16 h = __float2bfloat16_rn(v);
        float r = v - __bfloat162float(h);
        size_t o = (size_t)(n0 + ty + 8 * i) * Hh + k0 + tx;
        Th[o] = h;
        Tl[o] = __float2bfloat16_rn(r);
    }
}

// ---------------------------------------------------------------------------
// HMMA split-bf16 GEMM: C[M,N] = A[M,K] @ B[N,K]^T + bias
// CTA 128x128, BK=32, 8 warps (warp tile 64x32), cp.async double buffer.
// ---------------------------------------------------------------------------
#define BKg   32
#define PADR  40                         // halfs per smem row (conflict-free ldmatrix)
#define TILE_HALFS (128 * PADR)          // 5120
#define STAGE_HALFS (4 * TILE_HALFS)     // Ah, Al, Bh, Bl
#define GEMM_SMEM_BYTES (2 * STAGE_HALFS * 2)

__device__ __forceinline__ void stage_load(uint32_t sb,
    const __nv_bfloat16* __restrict__ Ah, const __nv_bfloat16* __restrict__ Al,
    const __nv_bfloat16* __restrict__ Bh, const __nv_bfloat16* __restrict__ Bl,
    int bm, int bn, int k0, int tid)
{
    // per tile: 128 rows x 32 halfs (64B) = 512 x 16B chunks; 2 chunks/thread
    const int r = tid >> 1;              // 0..127
    const int c = (tid & 1) * 2;         // chunk col 0 or 2 (c*8 halfs)
#pragma unroll
    for (int cc = 0; cc < 2; cc++) {
        const uint32_t so = (uint32_t)(r * PADR + (c + cc) * 8) * 2;
        const size_t go = (size_t)k0 + (c + cc) * 8;
        cp16(sb + so,                      Ah + (size_t)(bm + r) * Hh + go);
        cp16(sb + TILE_HALFS * 2 + so,     Al + (size_t)(bm + r) * Hh + go);
        cp16(sb + TILE_HALFS * 4 + so,     Bh + (size_t)(bn + r) * Hh + go);
        cp16(sb + TILE_HALFS * 6 + so,     Bl + (size_t)(bn + r) * Hh + go);
    }
}

template <bool HEADMAJOR>
__global__ __launch_bounds__(256, 1)
void gemm_mma(const __nv_bfloat16* __restrict__ Ah, const __nv_bfloat16* __restrict__ Al,
              const __nv_bfloat16* __restrict__ Bh, const __nv_bfloat16* __restrict__ Bl,
              const float* __restrict__ bias, float* __restrict__ C)
{
    extern __shared__ __nv_bfloat16 smem[];
    const uint32_t sbase = smem_to_u32(smem);
    const int tid = threadIdx.x;
    const int wid = tid >> 5, lane = tid & 31;
    const int bn = blockIdx.x * 128, bm = blockIdx.y * 128;
    const int wm = (wid >> 2) * 64;      // warp row base in tile
    const int wn = (wid & 3) * 32;       // warp col base in tile

    float acc[4][4][4];
#pragma unroll
    for (int i = 0; i < 4; i++)
#pragma unroll
        for (int j = 0; j < 4; j++)
#pragma unroll
            for (int q = 0; q < 4; q++) acc[i][j][q] = 0.f;

    // prologue
    stage_load(sbase, Ah, Al, Bh, Bl, bm, bn, 0, tid);
    CP_COMMIT();
    CP_WAIT0();
    __syncthreads();

    // ldmatrix address components (within a tile, halfs):
    const int arow = lane & 15;                  // A: row within 16
    const int acol8 = (lane >> 4) << 3;          // A: col 0 or 8
    const int brow = lane & 7;                   // B: n row within 8
    const int bcol8 = ((lane >> 3) & 1) << 3;    // B: col 0 or 8

    const int NIT = Hh / BKg;                    // 64
    for (int kt = 0; kt < NIT; kt++) {
        const uint32_t sb = sbase + (uint32_t)((kt & 1) * STAGE_HALFS * 2);
        if (kt + 1 < NIT) {
            stage_load(sbase + (uint32_t)(((kt + 1) & 1) * STAGE_HALFS * 2),
                       Ah, Al, Bh, Bl, bm, bn, (kt + 1) * BKg, tid);
            CP_COMMIT();
        }

#pragma unroll
        for (int ks = 0; ks < 2; ks++) {
            const int k0 = ks * 16;
            uint32_t aH[4][4], aL[4][4], bH[4][2], bL[4][2];
#pragma unroll
            for (int mi = 0; mi < 4; mi++) {
                const uint32_t off =
                    (uint32_t)((wm + mi * 16 + arow) * PADR + k0 + acol8) * 2;
                ldm_x4(aH[mi][0], aH[mi][1], aH[mi][2], aH[mi][3], sb + off);
                ldm_x4(aL[mi][0], aL[mi][1], aL[mi][2], aL[mi][3],
                       sb + TILE_HALFS * 2 + off);
            }
#pragma unroll
            for (int ni = 0; ni < 4; ni++) {
                const uint32_t off =
                    (uint32_t)((wn + ni * 8 + brow) * PADR + k0 + bcol8) * 2;
                ldm_x2(bH[ni][0], bH[ni][1], sb + TILE_HALFS * 4 + off);
                ldm_x2(bL[ni][0], bL[ni][1], sb + TILE_HALFS * 6 + off);
            }
#pragma unroll
            for (int mi = 0; mi < 4; mi++)
#pragma unroll
                for (int ni = 0; ni < 4; ni++) {
                    mma_bf16(acc[mi][ni], aH[mi], bH[ni]);
                    mma_bf16(acc[mi][ni], aL[mi], bH[ni]);
                    mma_bf16(acc[mi][ni], aH[mi], bL[ni]);
                }
        }

        if (kt + 1 < NIT) CP_WAIT0();
        __syncthreads();
    }

    // Epilogue: c fragment rows lane>>2 (+8), cols 2*(lane&3)
    const int fr = lane >> 2;
    const int fc = (lane & 3) * 2;
#pragma unroll
    for (int mi = 0; mi < 4; mi++) {
#pragma unroll
        for (int ni = 0; ni < 4; ni++) {
            const int n0 = bn + wn + ni * 8 + fc;
            const float b0 = bias[n0], b1 = bias[n0 + 1];
#pragma unroll
            for (int half = 0; half < 2; half++) {
                const int m = bm + wm + mi * 16 + fr + half * 8;
                float2 w;
                w.x = acc[mi][ni][half * 2 + 0] + b0;
                w.y = acc[mi][ni][half * 2 + 1] + b1;
                if (HEADMAJOR) {
                    const int bb = m >> 11;
                    const int ss = m & (Ss - 1);
                    const int hh = n0 >> 7;
                    const int dd = n0 & (HDd - 1);
                    *(float2*)&C[(((size_t)(bb * NHh + hh) * Ss) + ss) * HDd + dd] = w;
                } else {
                    *(float2*)&C[(size_t)m * Hh + n0] = w;
                }
            }
        }
    }
}

// ---------------------------------------------------------------------------
// Flash-style causal attention (fp32 SIMT)
// ---------------------------------------------------------------------------
#define QT 64
#define KT 64
#define LDK 132
#define LDP 65
#define ATT_SMEM_FLOATS (QT * HDd + KT * LDK * 2 + QT * LDP + 3 * QT)
#define ATT_SMEM_BYTES (ATT_SMEM_FLOATS * 4)

__global__ __launch_bounds__(256) void attn_kernel(
    const float* __restrict__ gQ, const float* __restrict__ gK,
    const float* __restrict__ gV, float* __restrict__ gAO)
{
    extern __shared__ float sm[];
    float* Qs  = sm;
    float* Ks  = Qs + QT * HDd;
    float* Vs  = Ks + KT * LDK;
    float* Ps  = Vs + KT * LDK;
    float* m_s = Ps + QT * LDP;
    float* l_s = m_s + QT;
    float* al_s = l_s + QT;

    const int qt = blockIdx.x;
    const int h  = blockIdx.y;
    const int b  = blockIdx.z;
    const int tid = threadIdx.x;
    const float scale = 0.08838834764831845f;

    const size_t base = ((size_t)(b * NHh + h)) * Ss * HDd;
    const float* qp = gQ + base + (size_t)qt * QT * HDd;

    for (int idx = tid; idx < QT * HDd / 4; idx += 256) {
        float4 v = ((const float4*)qp)[idx];
        v.x *= scale; v.y *= scale; v.z *= scale; v.w *= scale;
        ((float4*)Qs)[idx] = v;
    }
    if (tid < QT) { m_s[tid] = -1e30f; l_s[tid] = 0.f; }

    float o[4][8];
#pragma unroll
    for (int i = 0; i < 4; i++)
#pragma unroll
        for (int j = 0; j < 8; j++) o[i][j] = 0.f;

    const int sy = (tid >> 4) * 4;
    const int sx = (tid & 15) * 4;
    const int rd = (tid & 15) * 8;
    __syncthreads();

    for (int kt = 0; kt <= qt; kt++) {
        const float* kp = gK + base + (size_t)kt * KT * HDd;
        const float* vp = gV + base + (size_t)kt * KT * HDd;
        for (int idx = tid; idx < KT * (HDd / 4); idx += 256) {
            const int r = idx >> 5;
            const int c = (idx & 31) * 4;
            *(float4*)&Ks[r * LDK + c] = ((const float4*)kp)[idx];
            *(float4*)&Vs[r * LDK + c] = ((const float4*)vp)[idx];
        }
        __syncthreads();

        float s[4][4];
#pragma unroll
        for (int i = 0; i < 4; i++)
#pragma unroll
            for (int j = 0; j < 4; j++) s[i][j] = 0.f;

#pragma unroll 8
        for (int kk = 0; kk < HDd; kk += 4) {
            float qa[4][4], ka[4][4];
#pragma unroll
            for (int i = 0; i < 4; i++) {
                float4 t = *(const float4*)&Qs[(sy + i) * HDd + kk];
                qa[i][0] = t.x; qa[i][1] = t.y; qa[i][2] = t.z; qa[i][3] = t.w;
            }
#pragma unroll
            for (int j = 0; j < 4; j++) {
                float4 t = *(const float4*)&Ks[(sx + j) * LDK + kk];
                ka[j][0] = t.x; ka[j][1] = t.y; ka[j][2] = t.z; ka[j][3] = t.w;
            }
#pragma unroll
            for (int i = 0; i < 4; i++)
#pragma unroll
                for (int j = 0; j < 4; j++) {
                    s[i][j] = fmaf(qa[i][0], ka[j][0], s[i][j]);
                    s[i][j] = fmaf(qa[i][1], ka[j][1], s[i][j]);
                    s[i][j] = fmaf(qa[i][2], ka[j][2], s[i][j]);
                    s[i][j] = fmaf(qa[i][3], ka[j][3], s[i][j]);
                }
        }

        const bool diag = (kt == qt);
#pragma unroll
        for (int i = 0; i < 4; i++)
#pragma unroll
            for (int j = 0; j < 4; j++) {
                float v = s[i][j];
                if (diag && (sx + j) > (sy + i)) v = -1e30f;
                Ps[(sy + i) * LDP + sx + j] = v;
            }
        __syncthreads();

        if (tid < QT) {
            const int r = tid;
            const float mo = m_s[r];
            float mx = mo;
            for (int c = 0; c < KT; c++) mx = fmaxf(mx, Ps[r * LDP + c]);
            const float al = __expf(mo - mx);
            float sum = 0.f;
            for (int c = 0; c < KT; c++) {
                float p = __expf(Ps[r * LDP + c] - mx);
                Ps[r * LDP + c] = p;
                sum += p;
            }
            m_s[r]  = mx;
            l_s[r]  = l_s[r] * al + sum;
            al_s[r] = al;
        }
        __syncthreads();

        float al[4];
#pragma unroll
        for (int i = 0; i < 4; i++) al[i] = al_s[sy + i];
#pragma unroll
        for (int i = 0; i < 4; i++)
#pragma unroll
            for (int j = 0; j < 8; j++) o[i][j] *= al[i];

#pragma unroll 8
        for (int k = 0; k < KT; k++) {
            float p[4];
#pragma unroll
            for (int i = 0; i < 4; i++) p[i] = Ps[(sy + i) * LDP + k];
            float4 v0 = *(const float4*)&Vs[k * LDK + rd];
            float4 v1 = *(const float4*)&Vs[k * LDK + rd + 4];
            float vv[8] = {v0.x, v0.y, v0.z, v0.w, v1.x, v1.y, v1.z, v1.w};
#pragma unroll
            for (int i = 0; i < 4; i++)
#pragma unroll
                for (int j = 0; j < 8; j++)
                    o[i][j] = fmaf(p[i], vv[j], o[i][j]);
        }
        __syncthreads();
    }

    const int qrow = qt * QT;
#pragma unroll
    for (int i = 0; i < 4; i++) {
        const float inv = 1.f / l_s[sy + i];
        const size_t off =
            ((size_t)(b * Ss) + qrow + sy + i) * Hh + h * HDd + rd;
        float4 w0, w1;
        w0.x = o[i][0] * inv; w0.y = o[i][1] * inv;
        w0.z = o[i][2] * inv; w0.w = o[i][3] * inv;
        w1.x = o[i][4] * inv; w1.y = o[i][5] * inv;
        w1.z = o[i][6] * inv; w1.w = o[i][7] * inv;
        *(float4*)&gAO[off]     = w0;
        *(float4*)&gAO[off + 4] = w1;
    }
}

// ---------------------------------------------------------------------------
extern "C" void kernel_launch(void* const* d_in, const int* in_sizes, int n_in,
                              void* d_out, int out_size)
{
    (void)in_sizes; (void)n_in; (void)out_size;
    const float* x  = (const float*)d_in[0];
    const float* wq = (const float*)d_in[2];
    const float* bq = (const float*)d_in[3];
    const float* wk = (const float*)d_in[4];
    const float* bk = (const float*)d_in[5];
    const float* wv = (const float*)d_in[6];
    const float* bv = (const float*)d_in[7];
    const float* wo = (const float*)d_in[8];
    const float* bo = (const float*)d_in[9];
    float* out = (float*)d_out;

    float *qP, *kP, *vP, *aP;
    cudaGetSymbolAddress((void**)&qP, g_Q);
    cudaGetSymbolAddress((void**)&kP, g_K);
    cudaGetSymbolAddress((void**)&vP, g_V);
    cudaGetSymbolAddress((void**)&aP, g_AO);
    __nv_bfloat16 *xh, *xl, *aoh, *aol, *wh, *wl;
    cudaGetSymbolAddress((void**)&xh,  g_Xh);
    cudaGetSymbolAddress((void**)&xl,  g_Xl);
    cudaGetSymbolAddress((void**)&aoh, g_AOh);
    cudaGetSymbolAddress((void**)&aol, g_AOl);
    cudaGetSymbolAddress((void**)&wh,  g_Wh);
    cudaGetSymbolAddress((void**)&wl,  g_Wl);
    const size_t WSZ = (size_t)Hh * Hh;

    static bool attr_set = false;
    if (!attr_set) {
        cudaFuncSetAttribute(gemm_mma<true>,
                             cudaFuncAttributeMaxDynamicSharedMemorySize, GEMM_SMEM_BYTES);
        cudaFuncSetAttribute(gemm_mma<false>,
                             cudaFuncAttributeMaxDynamicSharedMemorySize, GEMM_SMEM_BYTES);
        cudaFuncSetAttribute(attn_kernel,
                             cudaFuncAttributeMaxDynamicSharedMemorySize, ATT_SMEM_BYTES);
        attr_set = true;
    }

    const int N2 = Mm * Hh / 2;
    convert_split<<<(N2 + 255) / 256, 256>>>(
        (const float2*)x, (__nv_bfloat162*)xh, (__nv_bfloat162*)xl, N2);

    dim3 tg(Hh / 32, Hh / 32), tb(32, 8);
    transpose_split<<<tg, tb>>>(wq, wh + 0 * WSZ, wl + 0 * WSZ);
    transpose_split<<<tg, tb>>>(wk, wh + 1 * WSZ, wl + 1 * WSZ);
    transpose_split<<<tg, tb>>>(wv, wh + 2 * WSZ, wl + 2 * WSZ);
    transpose_split<<<tg, tb>>>(wo, wh + 3 * WSZ, wl + 3 * WSZ);

    dim3 gg(Hh / 128, Mm / 128);
    gemm_mma<true><<<gg, 256, GEMM_SMEM_BYTES>>>(xh, xl, wh + 0 * WSZ, wl + 0 * WSZ, bq, qP);
    gemm_mma<true><<<gg, 256, GEMM_SMEM_BYTES>>>(xh, xl, wh + 1 * WSZ, wl + 1 * WSZ, bk, kP);
    gemm_mma<true><<<gg, 256, GEMM_SMEM_BYTES>>>(xh, xl, wh + 2 * WSZ, wl + 2 * WSZ, bv, vP);

    attn_kernel<<<dim3(Ss / QT, NHh, Bb), 256, ATT_SMEM_BYTES>>>(qP, kP, vP, aP);

    convert_split<<<(N2 + 255) / 256, 256>>>(
        (const float2*)aP, (__nv_bfloat162*)aoh, (__nv_bfloat162*)aol, N2);
    gemm_mma<false><<<gg, 256, GEMM_SMEM_BYTES>>>(aoh, aol, wh + 3 * WSZ, wl + 3 * WSZ, bo, out);
}

// round 4
// speedup vs baseline: 2.7789x; 1.8480x over previous
#include <cuda_runtime.h>
#include <cuda_bf16.h>
#include <cstdint>

// Problem constants
#define Bb   2
#define Ss   2048
#define Hh   2048
#define NHh  16
#define HDd  128
#define Mm   4096   // B*S

// ---------------------------------------------------------------------------
// Scratch (device globals; no allocation allowed)
// ---------------------------------------------------------------------------
__device__ __nv_bfloat16 g_Xh[(size_t)Mm * Hh];
__device__ __nv_bfloat16 g_Xl[(size_t)Mm * Hh];
__device__ __nv_bfloat16 g_Qh[(size_t)Mm * Hh];
__device__ __nv_bfloat16 g_Ql[(size_t)Mm * Hh];
__device__ __nv_bfloat16 g_Kh[(size_t)Mm * Hh];
__device__ __nv_bfloat16 g_Kl[(size_t)Mm * Hh];
__device__ __nv_bfloat16 g_Vh[(size_t)Mm * Hh];
__device__ __nv_bfloat16 g_Vl[(size_t)Mm * Hh];
__device__ __nv_bfloat16 g_AOh[(size_t)Mm * Hh];
__device__ __nv_bfloat16 g_AOl[(size_t)Mm * Hh];
__device__ __nv_bfloat16 g_Wh[4][(size_t)Hh * Hh];
__device__ __nv_bfloat16 g_Wl[4][(size_t)Hh * Hh];

// ---------------------------------------------------------------------------
// PTX helpers (sm_80-level only: legal in compute_103 PTX)
// ---------------------------------------------------------------------------
__device__ __forceinline__ uint32_t smem_to_u32(const void* p) {
    uint32_t a;
    asm("{ .reg .u64 t; cvta.to.shared.u64 t, %1; cvt.u32.u64 %0, t; }"
        : "=r"(a) : "l"(p));
    return a;
}
__device__ __forceinline__ void cp16(uint32_t s, const void* g) {
    asm volatile("cp.async.cg.shared.global [%0], [%1], 16;" :: "r"(s), "l"(g));
}
#define CP_COMMIT() asm volatile("cp.async.commit_group;" ::: "memory")
#define CP_WAIT0()  asm volatile("cp.async.wait_group 0;" ::: "memory")
#define CP_WAIT1()  asm volatile("cp.async.wait_group 1;" ::: "memory")

__device__ __forceinline__ void ldm_x4(uint32_t& r0, uint32_t& r1, uint32_t& r2,
                                       uint32_t& r3, uint32_t addr) {
    asm volatile("ldmatrix.sync.aligned.m8n8.x4.shared.b16 {%0,%1,%2,%3}, [%4];"
                 : "=r"(r0), "=r"(r1), "=r"(r2), "=r"(r3) : "r"(addr));
}
__device__ __forceinline__ void ldm_x4t(uint32_t& r0, uint32_t& r1, uint32_t& r2,
                                        uint32_t& r3, uint32_t addr) {
    asm volatile("ldmatrix.sync.aligned.m8n8.x4.trans.shared.b16 {%0,%1,%2,%3}, [%4];"
                 : "=r"(r0), "=r"(r1), "=r"(r2), "=r"(r3) : "r"(addr));
}
__device__ __forceinline__ void ldm_x2(uint32_t& r0, uint32_t& r1, uint32_t addr) {
    asm volatile("ldmatrix.sync.aligned.m8n8.x2.shared.b16 {%0,%1}, [%2];"
                 : "=r"(r0), "=r"(r1) : "r"(addr));
}
__device__ __forceinline__ void mma_bf16(float* c, const uint32_t* a, const uint32_t* b) {
    asm volatile("mma.sync.aligned.m16n8k16.row.col.f32.bf16.bf16.f32 "
                 "{%0,%1,%2,%3}, {%4,%5,%6,%7}, {%8,%9}, {%0,%1,%2,%3};"
                 : "+f"(c[0]), "+f"(c[1]), "+f"(c[2]), "+f"(c[3])
                 : "r"(a[0]), "r"(a[1]), "r"(a[2]), "r"(a[3]), "r"(b[0]), "r"(b[1]));
}

// Fast exp2 on the FMA pipe (deg-5 Taylor, f in [-0.5,0.5]); rel err ~2.4e-6.
__device__ __forceinline__ float exp2p(float t) {
    t = fmaxf(t, -120.f);
    float fn = t + 12582912.f;                 // round to nearest int
    int   n  = __float_as_int(fn) - 0x4B400000;
    float f  = t - (fn - 12582912.f);
    float p  = 1.3333558146428443e-3f;
    p = fmaf(p, f, 9.6181291076284772e-3f);
    p = fmaf(p, f, 5.5504108664821580e-2f);
    p = fmaf(p, f, 2.4022650695910071e-1f);
    p = fmaf(p, f, 6.9314718055994531e-1f);
    p = fmaf(p, f, 1.0f);
    return p * __int_as_float((n + 127) << 23);
}

__device__ __forceinline__ uint32_t packbf(float x, float y) {
    __nv_bfloat162 t = __floats2bfloat162_rn(x, y);   // .x = x (low), .y = y (high)
    return *reinterpret_cast<uint32_t*>(&t);
}

// ---------------------------------------------------------------------------
// Split conversion: fp32 -> (bf16 hi, bf16 lo)
// ---------------------------------------------------------------------------
__global__ void convert_split(const float2* __restrict__ X,
                              __nv_bfloat162* __restrict__ Xh,
                              __nv_bfloat162* __restrict__ Xl, int n2)
{
    int i = blockIdx.x * blockDim.x + threadIdx.x;
    if (i >= n2) return;
    float2 v = X[i];
    __nv_bfloat16 h0 = __float2bfloat16_rn(v.x);
    __nv_bfloat16 h1 = __float2bfloat16_rn(v.y);
    float r0 = v.x - __bfloat162float(h0);
    float r1 = v.y - __bfloat162float(h1);
    Xh[i] = __nv_bfloat162(h0, h1);
    Xl[i] = __nv_bfloat162(__float2bfloat16_rn(r0), __float2bfloat16_rn(r1));
}

// Transpose + split: W[K,N] fp32 -> WT[N,K] bf16 hi/lo  (K=N=2048)
__global__ void transpose_split(const float* __restrict__ W,
                                __nv_bfloat16* __restrict__ Th,
                                __nv_bfloat16* __restrict__ Tl)
{
    __shared__ float t[32][33];
    const int n0 = blockIdx.x * 32, k0 = blockIdx.y * 32;
    const int tx = threadIdx.x, ty = threadIdx.y;   // (32, 8)
#pragma unroll
    for (int i = 0; i < 4; i++)
        t[ty + 8 * i][tx] = W[(size_t)(k0 + ty + 8 * i) * Hh + n0 + tx];
    __syncthreads();
#pragma unroll
    for (int i = 0; i < 4; i++) {
        float v = t[tx][ty + 8 * i];
        __nv_bfloat16 h = __float2bfloat16_rn(v);
        float r = v - __bfloat162float(h);
        size_t o = (size_t)(n0 + ty + 8 * i) * Hh + k0 + tx;
        Th[o] = h;
        Tl[o] = __float2bfloat16_rn(r);
    }
}

// ---------------------------------------------------------------------------
// HMMA split-bf16 GEMM: C[M,N] = A[M,K] @ B[N,K]^T + bias
// MODE 0: fp32 row-major out.  MODE 1: bf16 hi/lo head-major out.
// ---------------------------------------------------------------------------
#define BKg   32
#define PADR  40
#define TILE_HALFS (128 * PADR)
#define STAGE_HALFS (4 * TILE_HALFS)
#define GEMM_SMEM_BYTES (2 * STAGE_HALFS * 2)

__device__ __forceinline__ void stage_load(uint32_t sb,
    const __nv_bfloat16* __restrict__ Ah, const __nv_bfloat16* __restrict__ Al,
    const __nv_bfloat16* __restrict__ Bh, const __nv_bfloat16* __restrict__ Bl,
    int bm, int bn, int k0, int tid)
{
    const int r = tid >> 1;
    const int c = (tid & 1) * 2;
#pragma unroll
    for (int cc = 0; cc < 2; cc++) {
        const uint32_t so = (uint32_t)(r * PADR + (c + cc) * 8) * 2;
        const size_t go = (size_t)k0 + (c + cc) * 8;
        cp16(sb + so,                  Ah + (size_t)(bm + r) * Hh + go);
        cp16(sb + TILE_HALFS * 2 + so, Al + (size_t)(bm + r) * Hh + go);
        cp16(sb + TILE_HALFS * 4 + so, Bh + (size_t)(bn + r) * Hh + go);
        cp16(sb + TILE_HALFS * 6 + so, Bl + (size_t)(bn + r) * Hh + go);
    }
}

template <int MODE>
__global__ __launch_bounds__(256, 1)
void gemm_mma(const __nv_bfloat16* __restrict__ Ah, const __nv_bfloat16* __restrict__ Al,
              const __nv_bfloat16* __restrict__ Bh, const __nv_bfloat16* __restrict__ Bl,
              const float* __restrict__ bias, float* __restrict__ Cf,
              __nv_bfloat16* __restrict__ Ch, __nv_bfloat16* __restrict__ Cl)
{
    extern __shared__ __nv_bfloat16 smem[];
    const uint32_t sbase = smem_to_u32(smem);
    const int tid = threadIdx.x;
    const int wid = tid >> 5, lane = tid & 31;
    const int bn = blockIdx.x * 128, bm = blockIdx.y * 128;
    const int wm = (wid >> 2) * 64;
    const int wn = (wid & 3) * 32;

    float acc[4][4][4];
#pragma unroll
    for (int i = 0; i < 4; i++)
#pragma unroll
        for (int j = 0; j < 4; j++)
#pragma unroll
            for (int q = 0; q < 4; q++) acc[i][j][q] = 0.f;

    stage_load(sbase, Ah, Al, Bh, Bl, bm, bn, 0, tid);
    CP_COMMIT();
    CP_WAIT0();
    __syncthreads();

    const int arow = lane & 15;
    const int acol8 = (lane >> 4) << 3;
    const int brow = lane & 7;
    const int bcol8 = ((lane >> 3) & 1) << 3;

    const int NIT = Hh / BKg;
    for (int kt = 0; kt < NIT; kt++) {
        const uint32_t sb = sbase + (uint32_t)((kt & 1) * STAGE_HALFS * 2);
        if (kt + 1 < NIT) {
            stage_load(sbase + (uint32_t)(((kt + 1) & 1) * STAGE_HALFS * 2),
                       Ah, Al, Bh, Bl, bm, bn, (kt + 1) * BKg, tid);
            CP_COMMIT();
        }

#pragma unroll
        for (int ks = 0; ks < 2; ks++) {
            const int k0 = ks * 16;
            uint32_t aH[4][4], aL[4][4], bH[4][2], bL[4][2];
#pragma unroll
            for (int mi = 0; mi < 4; mi++) {
                const uint32_t off =
                    (uint32_t)((wm + mi * 16 + arow) * PADR + k0 + acol8) * 2;
                ldm_x4(aH[mi][0], aH[mi][1], aH[mi][2], aH[mi][3], sb + off);
                ldm_x4(aL[mi][0], aL[mi][1], aL[mi][2], aL[mi][3],
                       sb + TILE_HALFS * 2 + off);
            }
#pragma unroll
            for (int ni = 0; ni < 4; ni++) {
                const uint32_t off =
                    (uint32_t)((wn + ni * 8 + brow) * PADR + k0 + bcol8) * 2;
                ldm_x2(bH[ni][0], bH[ni][1], sb + TILE_HALFS * 4 + off);
                ldm_x2(bL[ni][0], bL[ni][1], sb + TILE_HALFS * 6 + off);
            }
#pragma unroll
            for (int mi = 0; mi < 4; mi++)
#pragma unroll
                for (int ni = 0; ni < 4; ni++) {
                    mma_bf16(acc[mi][ni], aH[mi], bH[ni]);
                    mma_bf16(acc[mi][ni], aL[mi], bH[ni]);
                    mma_bf16(acc[mi][ni], aH[mi], bL[ni]);
                }
        }

        if (kt + 1 < NIT) CP_WAIT0();
        __syncthreads();
    }

    const int fr = lane >> 2;
    const int fc = (lane & 3) * 2;
#pragma unroll
    for (int mi = 0; mi < 4; mi++) {
#pragma unroll
        for (int ni = 0; ni < 4; ni++) {
            const int n0 = bn + wn + ni * 8 + fc;
            const float b0 = bias[n0], b1 = bias[n0 + 1];
#pragma unroll
            for (int half = 0; half < 2; half++) {
                const int m = bm + wm + mi * 16 + fr + half * 8;
                float v0 = acc[mi][ni][half * 2 + 0] + b0;
                float v1 = acc[mi][ni][half * 2 + 1] + b1;
                if (MODE == 1) {
                    const int bb = m >> 11;
                    const int ss = m & (Ss - 1);
                    const int hh = n0 >> 7;
                    const int dd = n0 & (HDd - 1);
                    const size_t idx =
                        (((size_t)(bb * NHh + hh) * Ss) + ss) * HDd + dd;
                    __nv_bfloat16 h0 = __float2bfloat16_rn(v0);
                    __nv_bfloat16 h1 = __float2bfloat16_rn(v1);
                    float r0 = v0 - __bfloat162float(h0);
                    float r1 = v1 - __bfloat162float(h1);
                    *(__nv_bfloat162*)&Ch[idx] = __nv_bfloat162(h0, h1);
                    *(__nv_bfloat162*)&Cl[idx] = __nv_bfloat162(
                        __float2bfloat16_rn(r0), __float2bfloat16_rn(r1));
                } else {
                    float2 w; w.x = v0; w.y = v1;
                    *(float2*)&Cf[(size_t)m * Hh + n0] = w;
                }
            }
        }
    }
}

// ---------------------------------------------------------------------------
// HMMA flash attention (bf16-split QK^T and PV, FA2 online softmax)
// CTA: 128 q rows, 8 warps x 16 rows. KT=64, double-buffered cp.async.
// ---------------------------------------------------------------------------
#define AQT 128
#define AKT 64
#define PADV 136
#define KV_TILE_B  (AKT * PADV * 2)        // 17408 bytes per tile
#define KV_STAGE_B (4 * KV_TILE_B)         // Kh,Kl,Vh,Vl = 69632 bytes
#define ATT2_SMEM  (2 * KV_STAGE_B)        // 139264 bytes

__device__ __forceinline__ void stage_kv(uint32_t dst, size_t base, int kn0,
    const __nv_bfloat16* __restrict__ Kh, const __nv_bfloat16* __restrict__ Kl,
    const __nv_bfloat16* __restrict__ Vh, const __nv_bfloat16* __restrict__ Vl,
    int tid)
{
#pragma unroll
    for (int i = 0; i < 4; i++) {
        const int idx = i * 256 + tid;
        const int row = idx >> 4, ch = idx & 15;
        const uint32_t so = (uint32_t)(row * PADV + ch * 8) * 2;
        const size_t go = base + (size_t)(kn0 + row) * HDd + ch * 8;
        cp16(dst +                so, Kh + go);
        cp16(dst + KV_TILE_B     + so, Kl + go);
        cp16(dst + 2 * KV_TILE_B + so, Vh + go);
        cp16(dst + 3 * KV_TILE_B + so, Vl + go);
    }
}

__global__ __launch_bounds__(256, 1)
void attn_mma(const __nv_bfloat16* __restrict__ Qh, const __nv_bfloat16* __restrict__ Ql,
              const __nv_bfloat16* __restrict__ Kh, const __nv_bfloat16* __restrict__ Kl,
              const __nv_bfloat16* __restrict__ Vh, const __nv_bfloat16* __restrict__ Vl,
              __nv_bfloat16* __restrict__ AOh, __nv_bfloat16* __restrict__ AOl)
{
    extern __shared__ __nv_bfloat16 asmem[];
    const uint32_t sb = smem_to_u32(asmem);
    const int tid = threadIdx.x, wid = tid >> 5, lane = tid & 31;
    const int qi = (int)gridDim.x - 1 - (int)blockIdx.x;   // big tiles first
    const int hh = blockIdx.y, bb = blockIdx.z;
    const size_t base = ((size_t)(bb * NHh + hh)) * Ss * HDd;
    const int q0 = qi * AQT;
    const float Cs = 0.12751745210319466f;   // 128^-0.5 * log2(e)

    // ---- load Q fragments to registers (via smem staging) ----
    uint32_t qfh[8][4], qfl[8][4];
    {
        const int qrow = wid * 16 + (lane & 15);
        const int qc8 = (lane >> 4) << 3;
#pragma unroll
        for (int i = 0; i < 8; i++) {
            const int idx = i * 256 + tid;
            const int row = idx >> 4, ch = idx & 15;
            cp16(sb + (uint32_t)(row * PADV + ch * 8) * 2,
                 Qh + base + (size_t)(q0 + row) * HDd + ch * 8);
        }
        CP_COMMIT(); CP_WAIT0(); __syncthreads();
#pragma unroll
        for (int kk = 0; kk < 8; kk++)
            ldm_x4(qfh[kk][0], qfh[kk][1], qfh[kk][2], qfh[kk][3],
                   sb + (uint32_t)(qrow * PADV + kk * 16 + qc8) * 2);
        __syncthreads();
#pragma unroll
        for (int i = 0; i < 8; i++) {
            const int idx = i * 256 + tid;
            const int row = idx >> 4, ch = idx & 15;
            cp16(sb + (uint32_t)(row * PADV + ch * 8) * 2,
                 Ql + base + (size_t)(q0 + row) * HDd + ch * 8);
        }
        CP_COMMIT(); CP_WAIT0(); __syncthreads();
#pragma unroll
        for (int kk = 0; kk < 8; kk++)
            ldm_x4(qfl[kk][0], qfl[kk][1], qfl[kk][2], qfl[kk][3],
                   sb + (uint32_t)(qrow * PADV + kk * 16 + qc8) * 2);
        __syncthreads();
    }

    float O[16][4];
#pragma unroll
    for (int i = 0; i < 16; i++)
#pragma unroll
        for (int j = 0; j < 4; j++) O[i][j] = 0.f;
    float m0 = -1e30f, m1 = -1e30f, l0 = 0.f, l1 = 0.f;

    const int nkt = 2 * qi + 2;
    stage_kv(sb, base, 0, Kh, Kl, Vh, Vl, tid);
    CP_COMMIT();

    for (int kt = 0; kt < nkt; kt++) {
        const uint32_t cur = sb + (uint32_t)((kt & 1) * KV_STAGE_B);
        if (kt + 1 < nkt) {
            stage_kv(sb + (uint32_t)(((kt + 1) & 1) * KV_STAGE_B), base,
                     (kt + 1) * AKT, Kh, Kl, Vh, Vl, tid);
            CP_COMMIT();
            CP_WAIT1();
        } else {
            CP_WAIT0();
        }
        __syncthreads();

        const uint32_t KsH = cur, KsL = cur + KV_TILE_B;
        const uint32_t VsH = cur + 2 * KV_TILE_B, VsL = cur + 3 * KV_TILE_B;

        // ---- scores: c[nf][4], nf = 0..7 over 64 keys ----
        float c[8][4];
#pragma unroll
        for (int i = 0; i < 8; i++)
#pragma unroll
            for (int j = 0; j < 4; j++) c[i][j] = 0.f;

#pragma unroll
        for (int kk = 0; kk < 8; kk++) {
            const uint32_t kc = (uint32_t)(kk * 16 + ((lane >> 3) & 1) * 8) * 2;
#pragma unroll
            for (int nfp = 0; nfp < 4; nfp++) {
                const uint32_t nrow =
                    (uint32_t)(nfp * 16 + ((lane >> 4) << 3) + (lane & 7));
                const uint32_t off = nrow * (PADV * 2) + kc;
                uint32_t h0, h1, h2, h3, e0, e1, e2, e3;
                ldm_x4(h0, h1, h2, h3, KsH + off);
                ldm_x4(e0, e1, e2, e3, KsL + off);
                uint32_t bA[2] = {h0, h1}, bB[2] = {h2, h3};
                uint32_t cA[2] = {e0, e1}, cB[2] = {e2, e3};
                mma_bf16(c[2 * nfp],     qfh[kk], bA);
                mma_bf16(c[2 * nfp],     qfl[kk], bA);
                mma_bf16(c[2 * nfp],     qfh[kk], cA);
                mma_bf16(c[2 * nfp + 1], qfh[kk], bB);
                mma_bf16(c[2 * nfp + 1], qfl[kk], bB);
                mma_bf16(c[2 * nfp + 1], qfh[kk], cB);
            }
        }

        // ---- causal mask ----
        const int kn0 = kt * AKT;
        if (kn0 + AKT - 1 > q0 + wid * 16) {
            const int row0 = q0 + wid * 16 + (lane >> 2);
            const int col0 = kn0 + (lane & 3) * 2;
#pragma unroll
            for (int nf = 0; nf < 8; nf++) {
                const int cb = col0 + nf * 8;
                if (cb     > row0)     c[nf][0] = -1e30f;
                if (cb + 1 > row0)     c[nf][1] = -1e30f;
                if (cb     > row0 + 8) c[nf][2] = -1e30f;
                if (cb + 1 > row0 + 8) c[nf][3] = -1e30f;
            }
        }

        // ---- online softmax ----
        float rm0 = -1e30f, rm1 = -1e30f;
#pragma unroll
        for (int nf = 0; nf < 8; nf++) {
            rm0 = fmaxf(rm0, fmaxf(c[nf][0], c[nf][1]));
            rm1 = fmaxf(rm1, fmaxf(c[nf][2], c[nf][3]));
        }
        rm0 = fmaxf(rm0, __shfl_xor_sync(0xffffffffu, rm0, 1));
        rm0 = fmaxf(rm0, __shfl_xor_sync(0xffffffffu, rm0, 2));
        rm1 = fmaxf(rm1, __shfl_xor_sync(0xffffffffu, rm1, 1));
        rm1 = fmaxf(rm1, __shfl_xor_sync(0xffffffffu, rm1, 2));
        const float mn0 = fmaxf(m0, rm0), mn1 = fmaxf(m1, rm1);
        const float a0 = exp2p((m0 - mn0) * Cs);
        const float a1 = exp2p((m1 - mn1) * Cs);
        m0 = mn0; m1 = mn1;

        float rs0 = 0.f, rs1 = 0.f;
#pragma unroll
        for (int nf = 0; nf < 8; nf++) {
            c[nf][0] = exp2p((c[nf][0] - mn0) * Cs);
            c[nf][1] = exp2p((c[nf][1] - mn0) * Cs);
            c[nf][2] = exp2p((c[nf][2] - mn1) * Cs);
            c[nf][3] = exp2p((c[nf][3] - mn1) * Cs);
            rs0 += c[nf][0] + c[nf][1];
            rs1 += c[nf][2] + c[nf][3];
        }
        rs0 += __shfl_xor_sync(0xffffffffu, rs0, 1);
        rs0 += __shfl_xor_sync(0xffffffffu, rs0, 2);
        rs1 += __shfl_xor_sync(0xffffffffu, rs1, 1);
        rs1 += __shfl_xor_sync(0xffffffffu, rs1, 2);
        l0 = l0 * a0 + rs0;
        l1 = l1 * a1 + rs1;

#pragma unroll
        for (int i = 0; i < 16; i++) {
            O[i][0] *= a0; O[i][1] *= a0; O[i][2] *= a1; O[i][3] *= a1;
        }

        // ---- pack P fragments (bf16 hi/lo) ----
        uint32_t pah[4][4], pal[4][4];
#pragma unroll
        for (int k2 = 0; k2 < 4; k2++) {
#pragma unroll
            for (int q = 0; q < 4; q++) {
                const int nf = 2 * k2 + (q >> 1);
                const int e  = (q & 1) * 2;
                const float x = c[nf][e], y = c[nf][e + 1];
                pah[k2][q] = packbf(x, y);
                const float xh = __bfloat162float(__float2bfloat16_rn(x));
                const float yh = __bfloat162float(__float2bfloat16_rn(y));
                pal[k2][q] = packbf(x - xh, y - yh);
            }
        }

        // ---- O += P @ V ----
#pragma unroll
        for (int k2 = 0; k2 < 4; k2++) {
            const uint32_t vr =
                (uint32_t)(k2 * 16 + (lane & 7) + ((lane >> 3) & 1) * 8);
#pragma unroll
            for (int nfp = 0; nfp < 8; nfp++) {
                const uint32_t vc = (uint32_t)(nfp * 16 + ((lane >> 4) << 3));
                const uint32_t off = (vr * PADV + vc) * 2;
                uint32_t h0, h1, h2, h3, e0, e1, e2, e3;
                ldm_x4t(h0, h1, h2, h3, VsH + off);
                ldm_x4t(e0, e1, e2, e3, VsL + off);
                uint32_t bA[2] = {h0, h1}, bB[2] = {h2, h3};
                uint32_t cA[2] = {e0, e1}, cB[2] = {e2, e3};
                mma_bf16(O[2 * nfp],     pah[k2], bA);
                mma_bf16(O[2 * nfp],     pal[k2], bA);
                mma_bf16(O[2 * nfp],     pah[k2], cA);
                mma_bf16(O[2 * nfp + 1], pah[k2], bB);
                mma_bf16(O[2 * nfp + 1], pal[k2], bB);
                mma_bf16(O[2 * nfp + 1], pah[k2], cB);
            }
        }
        __syncthreads();
    }

    // ---- epilogue: normalize, split bf16, write AO hi/lo [B,S,H] ----
    const float inv0 = 1.f / l0, inv1 = 1.f / l1;
    const int srow0 = q0 + wid * 16 + (lane >> 2);
#pragma unroll
    for (int nf = 0; nf < 16; nf++) {
        const int col = hh * HDd + nf * 8 + (lane & 3) * 2;
        const size_t o0 = ((size_t)(bb * Ss) + srow0) * Hh + col;
        const size_t o1 = o0 + (size_t)8 * Hh;
        float v0 = O[nf][0] * inv0, v1 = O[nf][1] * inv0;
        float v2 = O[nf][2] * inv1, v3 = O[nf][3] * inv1;
        float h0 = __bfloat162float(__float2bfloat16_rn(v0));
        float h1 = __bfloat162float(__float2bfloat16_rn(v1));
        float h2 = __bfloat162float(__float2bfloat16_rn(v2));
        float h3 = __bfloat162float(__float2bfloat16_rn(v3));
        *(uint32_t*)&AOh[o0] = packbf(v0, v1);
        *(uint32_t*)&AOl[o0] = packbf(v0 - h0, v1 - h1);
        *(uint32_t*)&AOh[o1] = packbf(v2, v3);
        *(uint32_t*)&AOl[o1] = packbf(v2 - h2, v3 - h3);
    }
}

// ---------------------------------------------------------------------------
extern "C" void kernel_launch(void* const* d_in, const int* in_sizes, int n_in,
                              void* d_out, int out_size)
{
    (void)in_sizes; (void)n_in; (void)out_size;
    const float* x  = (const float*)d_in[0];
    const float* wq = (const float*)d_in[2];
    const float* bq = (const float*)d_in[3];
    const float* wk = (const float*)d_in[4];
    const float* bk = (const float*)d_in[5];
    const float* wv = (const float*)d_in[6];
    const float* bv = (const float*)d_in[7];
    const float* wo = (const float*)d_in[8];
    const float* bo = (const float*)d_in[9];
    float* out = (float*)d_out;

    __nv_bfloat16 *xh, *xl, *aoh, *aol, *wh, *wl;
    __nv_bfloat16 *qh, *ql, *kh, *kl, *vh, *vl;
    cudaGetSymbolAddress((void**)&xh,  g_Xh);
    cudaGetSymbolAddress((void**)&xl,  g_Xl);
    cudaGetSymbolAddress((void**)&aoh, g_AOh);
    cudaGetSymbolAddress((void**)&aol, g_AOl);
    cudaGetSymbolAddress((void**)&wh,  g_Wh);
    cudaGetSymbolAddress((void**)&wl,  g_Wl);
    cudaGetSymbolAddress((void**)&qh,  g_Qh);
    cudaGetSymbolAddress((void**)&ql,  g_Ql);
    cudaGetSymbolAddress((void**)&kh,  g_Kh);
    cudaGetSymbolAddress((void**)&kl,  g_Kl);
    cudaGetSymbolAddress((void**)&vh,  g_Vh);
    cudaGetSymbolAddress((void**)&vl,  g_Vl);
    const size_t WSZ = (size_t)Hh * Hh;

    static bool attr_set = false;
    if (!attr_set) {
        cudaFuncSetAttribute(gemm_mma<0>,
                             cudaFuncAttributeMaxDynamicSharedMemorySize, GEMM_SMEM_BYTES);
        cudaFuncSetAttribute(gemm_mma<1>,
                             cudaFuncAttributeMaxDynamicSharedMemorySize, GEMM_SMEM_BYTES);
        cudaFuncSetAttribute(attn_mma,
                             cudaFuncAttributeMaxDynamicSharedMemorySize, ATT2_SMEM);
        attr_set = true;
    }

    const int N2 = Mm * Hh / 2;
    convert_split<<<(N2 + 255) / 256, 256>>>(
        (const float2*)x, (__nv_bfloat162*)xh, (__nv_bfloat162*)xl, N2);

    dim3 tg(Hh / 32, Hh / 32), tb(32, 8);
    transpose_split<<<tg, tb>>>(wq, wh + 0 * WSZ, wl + 0 * WSZ);
    transpose_split<<<tg, tb>>>(wk, wh + 1 * WSZ, wl + 1 * WSZ);
    transpose_split<<<tg, tb>>>(wv, wh + 2 * WSZ, wl + 2 * WSZ);
    transpose_split<<<tg, tb>>>(wo, wh + 3 * WSZ, wl + 3 * WSZ);

    dim3 gg(Hh / 128, Mm / 128);
    gemm_mma<1><<<gg, 256, GEMM_SMEM_BYTES>>>(xh, xl, wh + 0 * WSZ, wl + 0 * WSZ,
                                              bq, nullptr, qh, ql);
    gemm_mma<1><<<gg, 256, GEMM_SMEM_BYTES>>>(xh, xl, wh + 1 * WSZ, wl + 1 * WSZ,
                                              bk, nullptr, kh, kl);
    gemm_mma<1><<<gg, 256, GEMM_SMEM_BYTES>>>(xh, xl, wh + 2 * WSZ, wl + 2 * WSZ,
                                              bv, nullptr, vh, vl);

    attn_mma<<<dim3(Ss / AQT, NHh, Bb), 256, ATT2_SMEM>>>(qh, ql, kh, kl, vh, vl,
                                                          aoh, aol);

    gemm_mma<0><<<gg, 256, GEMM_SMEM_BYTES>>>(aoh, aol, wh + 3 * WSZ, wl + 3 * WSZ,
                                              bo, out, nullptr, nullptr);
}

// round 5
// speedup vs baseline: 3.7659x; 1.3552x over previous
#include <cuda_runtime.h>
#include <cuda_fp16.h>
#include <cstdint>

// Problem constants
#define Bb   2
#define Ss   2048
#define Hh   2048
#define NHh  16
#define HDd  128
#define Mm   4096   // B*S

// ---------------------------------------------------------------------------
// Scratch (device globals; no allocation allowed)
// ---------------------------------------------------------------------------
__device__ __half g_Xh[(size_t)Mm * Hh];
__device__ __half g_Xl[(size_t)Mm * Hh];
__device__ __half g_Qh[(size_t)Mm * Hh];
__device__ __half g_Ql[(size_t)Mm * Hh];
__device__ __half g_Ks[(size_t)Mm * Hh];
__device__ __half g_Vs[(size_t)Mm * Hh];
__device__ __half g_AOh[(size_t)Mm * Hh];
__device__ __half g_AOl[(size_t)Mm * Hh];
__device__ __half g_Wt[4][(size_t)Hh * Hh];

// ---------------------------------------------------------------------------
// PTX helpers (sm_80-level only: legal in compute_103 PTX)
// ---------------------------------------------------------------------------
__device__ __forceinline__ uint32_t smem_to_u32(const void* p) {
    uint32_t a;
    asm("{ .reg .u64 t; cvta.to.shared.u64 t, %1; cvt.u32.u64 %0, t; }"
        : "=r"(a) : "l"(p));
    return a;
}
__device__ __forceinline__ void cp16(uint32_t s, const void* g) {
    asm volatile("cp.async.cg.shared.global [%0], [%1], 16;" :: "r"(s), "l"(g));
}
#define CP_COMMIT() asm volatile("cp.async.commit_group;" ::: "memory")
#define CP_WAIT0()  asm volatile("cp.async.wait_group 0;" ::: "memory")
#define CP_WAIT1()  asm volatile("cp.async.wait_group 1;" ::: "memory")

__device__ __forceinline__ void ldm_x4(uint32_t& r0, uint32_t& r1, uint32_t& r2,
                                       uint32_t& r3, uint32_t addr) {
    asm volatile("ldmatrix.sync.aligned.m8n8.x4.shared.b16 {%0,%1,%2,%3}, [%4];"
                 : "=r"(r0), "=r"(r1), "=r"(r2), "=r"(r3) : "r"(addr));
}
__device__ __forceinline__ void ldm_x4t(uint32_t& r0, uint32_t& r1, uint32_t& r2,
                                        uint32_t& r3, uint32_t addr) {
    asm volatile("ldmatrix.sync.aligned.m8n8.x4.trans.shared.b16 {%0,%1,%2,%3}, [%4];"
                 : "=r"(r0), "=r"(r1), "=r"(r2), "=r"(r3) : "r"(addr));
}
__device__ __forceinline__ void ldm_x2(uint32_t& r0, uint32_t& r1, uint32_t addr) {
    asm volatile("ldmatrix.sync.aligned.m8n8.x2.shared.b16 {%0,%1}, [%2];"
                 : "=r"(r0), "=r"(r1) : "r"(addr));
}
__device__ __forceinline__ void mma_f16(float* c, const uint32_t* a, const uint32_t* b) {
    asm volatile("mma.sync.aligned.m16n8k16.row.col.f32.f16.f16.f32 "
                 "{%0,%1,%2,%3}, {%4,%5,%6,%7}, {%8,%9}, {%0,%1,%2,%3};"
                 : "+f"(c[0]), "+f"(c[1]), "+f"(c[2]), "+f"(c[3])
                 : "r"(a[0]), "r"(a[1]), "r"(a[2]), "r"(a[3]), "r"(b[0]), "r"(b[1]));
}

// Fast exp2 on the FMA pipe (deg-5 poly, f in [-0.5,0.5]); rel err ~2.4e-6.
__device__ __forceinline__ float exp2p(float t) {
    t = fmaxf(t, -120.f);
    float fn = t + 12582912.f;
    int   n  = __float_as_int(fn) - 0x4B400000;
    float f  = t - (fn - 12582912.f);
    float p  = 1.3333558146428443e-3f;
    p = fmaf(p, f, 9.6181291076284772e-3f);
    p = fmaf(p, f, 5.5504108664821580e-2f);
    p = fmaf(p, f, 2.4022650695910071e-1f);
    p = fmaf(p, f, 6.9314718055994531e-1f);
    p = fmaf(p, f, 1.0f);
    return p * __int_as_float((n + 127) << 23);
}

__device__ __forceinline__ uint32_t packh(float x, float y) {
    __half2 t = __floats2half2_rn(x, y);
    return *reinterpret_cast<uint32_t*>(&t);
}

// ---------------------------------------------------------------------------
// Conversions
// ---------------------------------------------------------------------------
__global__ void convert_split(const float2* __restrict__ X,
                              __half2* __restrict__ Xh,
                              __half2* __restrict__ Xl, int n2)
{
    int i = blockIdx.x * blockDim.x + threadIdx.x;
    if (i >= n2) return;
    float2 v = X[i];
    __half h0 = __float2half_rn(v.x);
    __half h1 = __float2half_rn(v.y);
    float r0 = v.x - __half2float(h0);
    float r1 = v.y - __half2float(h1);
    Xh[i] = __half2(h0, h1);
    Xl[i] = __half2(__float2half_rn(r0), __float2half_rn(r1));
}

// Transpose + convert: W[K,N] fp32 -> WT[N,K] fp16  (K=N=2048)
__global__ void transpose_convert(const float* __restrict__ W,
                                  __half* __restrict__ T)
{
    __shared__ float t[32][33];
    const int n0 = blockIdx.x * 32, k0 = blockIdx.y * 32;
    const int tx = threadIdx.x, ty = threadIdx.y;   // (32, 8)
#pragma unroll
    for (int i = 0; i < 4; i++)
        t[ty + 8 * i][tx] = W[(size_t)(k0 + ty + 8 * i) * Hh + n0 + tx];
    __syncthreads();
#pragma unroll
    for (int i = 0; i < 4; i++)
        T[(size_t)(n0 + ty + 8 * i) * Hh + k0 + tx] =
            __float2half_rn(t[tx][ty + 8 * i]);
}

// ---------------------------------------------------------------------------
// HMMA fp16 GEMM, A split (hi+lo), B single: C = (Ah+Al)[M,K] @ B[N,K]^T + bias
// CTA 128x128, BK=32, 8 warps (warp tile 64x32), 3-stage cp.async pipeline.
// MODE 0: fp32 row-major.  MODE 1: fp16 hi/lo head-major.  MODE 2: fp16 head-major.
// ---------------------------------------------------------------------------
#define BKg   32
#define PADR  40
#define TILE_HALFS (128 * PADR)
#define STAGE_B ((uint32_t)(3 * TILE_HALFS * 2))   // Ah, Al, B = 30720 bytes
#define GEMM_SMEM_BYTES (3 * STAGE_B)

__device__ __forceinline__ void stage_load(uint32_t sb,
    const __half* __restrict__ Ah, const __half* __restrict__ Al,
    const __half* __restrict__ Bs, int bm, int bn, int k0, int tid)
{
    const int r = tid >> 1;
    const int c = (tid & 1) * 2;
#pragma unroll
    for (int cc = 0; cc < 2; cc++) {
        const uint32_t so = (uint32_t)(r * PADR + (c + cc) * 8) * 2;
        const size_t go = (size_t)k0 + (c + cc) * 8;
        cp16(sb + so,                  Ah + (size_t)(bm + r) * Hh + go);
        cp16(sb + TILE_HALFS * 2 + so, Al + (size_t)(bm + r) * Hh + go);
        cp16(sb + TILE_HALFS * 4 + so, Bs + (size_t)(bn + r) * Hh + go);
    }
}

template <int MODE>
__global__ __launch_bounds__(256, 1)
void gemm_mma(const __half* __restrict__ Ah, const __half* __restrict__ Al,
              const __half* __restrict__ Bs, const float* __restrict__ bias,
              float* __restrict__ Cf, __half* __restrict__ Ch,
              __half* __restrict__ Cl)
{
    extern __shared__ __half smem[];
    const uint32_t sbase = smem_to_u32(smem);
    const int tid = threadIdx.x;
    const int wid = tid >> 5, lane = tid & 31;
    const int bn = blockIdx.x * 128, bm = blockIdx.y * 128;
    const int wm = (wid >> 2) * 64;
    const int wn = (wid & 3) * 32;

    float acc[4][4][4];
#pragma unroll
    for (int i = 0; i < 4; i++)
#pragma unroll
        for (int j = 0; j < 4; j++)
#pragma unroll
            for (int q = 0; q < 4; q++) acc[i][j][q] = 0.f;

    const int NIT = Hh / BKg;   // 64
    // 3-stage prologue
    stage_load(sbase, Ah, Al, Bs, bm, bn, 0, tid);
    CP_COMMIT();
    stage_load(sbase + STAGE_B, Ah, Al, Bs, bm, bn, BKg, tid);
    CP_COMMIT();
    CP_WAIT1();                  // stage 0 ready
    __syncthreads();

    const int arow = lane & 15;
    const int acol8 = (lane >> 4) << 3;
    const int brow = lane & 7;
    const int bcol8 = ((lane >> 3) & 1) << 3;

    for (int kt = 0; kt < NIT; kt++) {
        const uint32_t sb = sbase + (uint32_t)(kt % 3) * STAGE_B;
        if (kt + 2 < NIT) {
            stage_load(sbase + (uint32_t)((kt + 2) % 3) * STAGE_B,
                       Ah, Al, Bs, bm, bn, (kt + 2) * BKg, tid);
            CP_COMMIT();
        }

#pragma unroll
        for (int ks = 0; ks < 2; ks++) {
            const int k0 = ks * 16;
            uint32_t aH[4][4], aL[4][4], bF[4][2];
#pragma unroll
            for (int mi = 0; mi < 4; mi++) {
                const uint32_t off =
                    (uint32_t)((wm + mi * 16 + arow) * PADR + k0 + acol8) * 2;
                ldm_x4(aH[mi][0], aH[mi][1], aH[mi][2], aH[mi][3], sb + off);
                ldm_x4(aL[mi][0], aL[mi][1], aL[mi][2], aL[mi][3],
                       sb + TILE_HALFS * 2 + off);
            }
#pragma unroll
            for (int ni = 0; ni < 4; ni++) {
                const uint32_t off =
                    (uint32_t)((wn + ni * 8 + brow) * PADR + k0 + bcol8) * 2;
                ldm_x2(bF[ni][0], bF[ni][1], sb + TILE_HALFS * 4 + off);
            }
#pragma unroll
            for (int mi = 0; mi < 4; mi++)
#pragma unroll
                for (int ni = 0; ni < 4; ni++) {
                    mma_f16(acc[mi][ni], aH[mi], bF[ni]);
                    mma_f16(acc[mi][ni], aL[mi], bF[ni]);
                }
        }

        if (kt + 1 < NIT) {
            if (kt + 2 < NIT) { CP_WAIT1(); } else { CP_WAIT0(); }
        }
        __syncthreads();
    }

    const int fr = lane >> 2;
    const int fc = (lane & 3) * 2;
#pragma unroll
    for (int mi = 0; mi < 4; mi++) {
#pragma unroll
        for (int ni = 0; ni < 4; ni++) {
            const int n0 = bn + wn + ni * 8 + fc;
            const float b0 = bias[n0], b1 = bias[n0 + 1];
#pragma unroll
            for (int half = 0; half < 2; half++) {
                const int m = bm + wm + mi * 16 + fr + half * 8;
                float v0 = acc[mi][ni][half * 2 + 0] + b0;
                float v1 = acc[mi][ni][half * 2 + 1] + b1;
                if (MODE == 0) {
                    float2 w; w.x = v0; w.y = v1;
                    *(float2*)&Cf[(size_t)m * Hh + n0] = w;
                } else {
                    const int bb = m >> 11;
                    const int ss = m & (Ss - 1);
                    const int hh = n0 >> 7;
                    const int dd = n0 & (HDd - 1);
                    const size_t idx =
                        (((size_t)(bb * NHh + hh) * Ss) + ss) * HDd + dd;
                    if (MODE == 1) {
                        __half h0 = __float2half_rn(v0);
                        __half h1 = __float2half_rn(v1);
                        float r0 = v0 - __half2float(h0);
                        float r1 = v1 - __half2float(h1);
                        *(__half2*)&Ch[idx] = __half2(h0, h1);
                        *(__half2*)&Cl[idx] = __half2(
                            __float2half_rn(r0), __float2half_rn(r1));
                    } else {
                        *(__half2*)&Ch[idx] = __floats2half2_rn(v0, v1);
                    }
                }
            }
        }
    }
}

// ---------------------------------------------------------------------------
// HMMA fp16 flash attention: Q split (2-MMA scores), K/V single, P split (2-MMA PV)
// CTA: 128 q rows, 8 warps x 16 rows. KT=64, double-buffered cp.async.
// ---------------------------------------------------------------------------
#define AQT 128
#define AKT 64
#define PADV 136
#define KV_TILE_B  (AKT * PADV * 2)        // 17408 bytes
#define KV_STAGE_B (2 * KV_TILE_B)         // K, V = 34816 bytes
#define ATT2_SMEM  (2 * KV_STAGE_B)        // 69632 bytes

__device__ __forceinline__ void stage_kv(uint32_t dst, size_t base, int kn0,
    const __half* __restrict__ Ks, const __half* __restrict__ Vs, int tid)
{
#pragma unroll
    for (int i = 0; i < 4; i++) {
        const int idx = i * 256 + tid;
        const int row = idx >> 4, ch = idx & 15;
        const uint32_t so = (uint32_t)(row * PADV + ch * 8) * 2;
        const size_t go = base + (size_t)(kn0 + row) * HDd + ch * 8;
        cp16(dst +             so, Ks + go);
        cp16(dst + KV_TILE_B + so, Vs + go);
    }
}

__global__ __launch_bounds__(256, 1)
void attn_mma(const __half* __restrict__ Qh, const __half* __restrict__ Ql,
              const __half* __restrict__ Ks, const __half* __restrict__ Vs,
              __half* __restrict__ AOh, __half* __restrict__ AOl)
{
    extern __shared__ __half asmem[];
    const uint32_t sb = smem_to_u32(asmem);
    const int tid = threadIdx.x, wid = tid >> 5, lane = tid & 31;
    const int qi = (int)gridDim.x - 1 - (int)blockIdx.x;   // big tiles first
    const int hh = blockIdx.y, bb = blockIdx.z;
    const size_t base = ((size_t)(bb * NHh + hh)) * Ss * HDd;
    const int q0 = qi * AQT;
    const float Cs = 0.12751745210319466f;   // 128^-0.5 * log2(e)

    // ---- load Q hi/lo fragments (staged through smem) ----
    uint32_t qfh[8][4], qfl[8][4];
    {
        const int qrow = wid * 16 + (lane & 15);
        const int qc8 = (lane >> 4) << 3;
#pragma unroll
        for (int i = 0; i < 8; i++) {
            const int idx = i * 256 + tid;
            const int row = idx >> 4, ch = idx & 15;
            cp16(sb + (uint32_t)(row * PADV + ch * 8) * 2,
                 Qh + base + (size_t)(q0 + row) * HDd + ch * 8);
        }
        CP_COMMIT(); CP_WAIT0(); __syncthreads();
#pragma unroll
        for (int kk = 0; kk < 8; kk++)
            ldm_x4(qfh[kk][0], qfh[kk][1], qfh[kk][2], qfh[kk][3],
                   sb + (uint32_t)(qrow * PADV + kk * 16 + qc8) * 2);
        __syncthreads();
#pragma unroll
        for (int i = 0; i < 8; i++) {
            const int idx = i * 256 + tid;
            const int row = idx >> 4, ch = idx & 15;
            cp16(sb + (uint32_t)(row * PADV + ch * 8) * 2,
                 Ql + base + (size_t)(q0 + row) * HDd + ch * 8);
        }
        CP_COMMIT(); CP_WAIT0(); __syncthreads();
#pragma unroll
        for (int kk = 0; kk < 8; kk++)
            ldm_x4(qfl[kk][0], qfl[kk][1], qfl[kk][2], qfl[kk][3],
                   sb + (uint32_t)(qrow * PADV + kk * 16 + qc8) * 2);
        __syncthreads();
    }

    float O[16][4];
#pragma unroll
    for (int i = 0; i < 16; i++)
#pragma unroll
        for (int j = 0; j < 4; j++) O[i][j] = 0.f;
    float m0 = -1e30f, m1 = -1e30f, l0 = 0.f, l1 = 0.f;

    const int nkt = 2 * qi + 2;
    stage_kv(sb, base, 0, Ks, Vs, tid);
    CP_COMMIT();

    for (int kt = 0; kt < nkt; kt++) {
        const uint32_t cur = sb + (uint32_t)((kt & 1) * KV_STAGE_B);
        if (kt + 1 < nkt) {
            stage_kv(sb + (uint32_t)(((kt + 1) & 1) * KV_STAGE_B), base,
                     (kt + 1) * AKT, Ks, Vs, tid);
            CP_COMMIT();
            CP_WAIT1();
        } else {
            CP_WAIT0();
        }
        __syncthreads();

        const uint32_t KsS = cur, VsS = cur + KV_TILE_B;

        // ---- scores ----
        float c[8][4];
#pragma unroll
        for (int i = 0; i < 8; i++)
#pragma unroll
            for (int j = 0; j < 4; j++) c[i][j] = 0.f;

#pragma unroll
        for (int kk = 0; kk < 8; kk++) {
            const uint32_t kc = (uint32_t)(kk * 16 + ((lane >> 3) & 1) * 8) * 2;
#pragma unroll
            for (int nfp = 0; nfp < 4; nfp++) {
                const uint32_t nrow =
                    (uint32_t)(nfp * 16 + ((lane >> 4) << 3) + (lane & 7));
                uint32_t h0, h1, h2, h3;
                ldm_x4(h0, h1, h2, h3, KsS + nrow * (PADV * 2) + kc);
                uint32_t bA[2] = {h0, h1}, bB[2] = {h2, h3};
                mma_f16(c[2 * nfp],     qfh[kk], bA);
                mma_f16(c[2 * nfp],     qfl[kk], bA);
                mma_f16(c[2 * nfp + 1], qfh[kk], bB);
                mma_f16(c[2 * nfp + 1], qfl[kk], bB);
            }
        }

        // ---- causal mask ----
        const int kn0 = kt * AKT;
        if (kn0 + AKT - 1 > q0 + wid * 16) {
            const int row0 = q0 + wid * 16 + (lane >> 2);
            const int col0 = kn0 + (lane & 3) * 2;
#pragma unroll
            for (int nf = 0; nf < 8; nf++) {
                const int cb = col0 + nf * 8;
                if (cb     > row0)     c[nf][0] = -1e30f;
                if (cb + 1 > row0)     c[nf][1] = -1e30f;
                if (cb     > row0 + 8) c[nf][2] = -1e30f;
                if (cb + 1 > row0 + 8) c[nf][3] = -1e30f;
            }
        }

        // ---- online softmax ----
        float rm0 = -1e30f, rm1 = -1e30f;
#pragma unroll
        for (int nf = 0; nf < 8; nf++) {
            rm0 = fmaxf(rm0, fmaxf(c[nf][0], c[nf][1]));
            rm1 = fmaxf(rm1, fmaxf(c[nf][2], c[nf][3]));
        }
        rm0 = fmaxf(rm0, __shfl_xor_sync(0xffffffffu, rm0, 1));
        rm0 = fmaxf(rm0, __shfl_xor_sync(0xffffffffu, rm0, 2));
        rm1 = fmaxf(rm1, __shfl_xor_sync(0xffffffffu, rm1, 1));
        rm1 = fmaxf(rm1, __shfl_xor_sync(0xffffffffu, rm1, 2));
        const float mn0 = fmaxf(m0, rm0), mn1 = fmaxf(m1, rm1);
        const float a0 = exp2p((m0 - mn0) * Cs);
        const float a1 = exp2p((m1 - mn1) * Cs);
        m0 = mn0; m1 = mn1;

        float rs0 = 0.f, rs1 = 0.f;
#pragma unroll
        for (int nf = 0; nf < 8; nf++) {
            c[nf][0] = exp2p((c[nf][0] - mn0) * Cs);
            c[nf][1] = exp2p((c[nf][1] - mn0) * Cs);
            c[nf][2] = exp2p((c[nf][2] - mn1) * Cs);
            c[nf][3] = exp2p((c[nf][3] - mn1) * Cs);
            rs0 += c[nf][0] + c[nf][1];
            rs1 += c[nf][2] + c[nf][3];
        }
        rs0 += __shfl_xor_sync(0xffffffffu, rs0, 1);
        rs0 += __shfl_xor_sync(0xffffffffu, rs0, 2);
        rs1 += __shfl_xor_sync(0xffffffffu, rs1, 1);
        rs1 += __shfl_xor_sync(0xffffffffu, rs1, 2);
        l0 = l0 * a0 + rs0;
        l1 = l1 * a1 + rs1;

#pragma unroll
        for (int i = 0; i < 16; i++) {
            O[i][0] *= a0; O[i][1] *= a0; O[i][2] *= a1; O[i][3] *= a1;
        }

        // ---- pack P fragments (fp16 hi/lo) ----
        uint32_t pah[4][4], pal[4][4];
#pragma unroll
        for (int k2 = 0; k2 < 4; k2++) {
#pragma unroll
            for (int q = 0; q < 4; q++) {
                const int nf = 2 * k2 + (q >> 1);
                const int e  = (q & 1) * 2;
                const float x = c[nf][e], y = c[nf][e + 1];
                pah[k2][q] = packh(x, y);
                const float xh = __half2float(__float2half_rn(x));
                const float yh = __half2float(__float2half_rn(y));
                pal[k2][q] = packh(x - xh, y - yh);
            }
        }

        // ---- O += P @ V ----
#pragma unroll
        for (int k2 = 0; k2 < 4; k2++) {
            const uint32_t vr =
                (uint32_t)(k2 * 16 + (lane & 7) + ((lane >> 3) & 1) * 8);
#pragma unroll
            for (int nfp = 0; nfp < 8; nfp++) {
                const uint32_t vc = (uint32_t)(nfp * 16 + ((lane >> 4) << 3));
                uint32_t h0, h1, h2, h3;
                ldm_x4t(h0, h1, h2, h3, VsS + (vr * PADV + vc) * 2);
                uint32_t bA[2] = {h0, h1}, bB[2] = {h2, h3};
                mma_f16(O[2 * nfp],     pah[k2], bA);
                mma_f16(O[2 * nfp],     pal[k2], bA);
                mma_f16(O[2 * nfp + 1], pah[k2], bB);
                mma_f16(O[2 * nfp + 1], pal[k2], bB);
            }
        }
        __syncthreads();
    }

    // ---- epilogue: normalize, split fp16, write AO hi/lo [B,S,H] ----
    const float inv0 = 1.f / l0, inv1 = 1.f / l1;
    const int srow0 = q0 + wid * 16 + (lane >> 2);
#pragma unroll
    for (int nf = 0; nf < 16; nf++) {
        const int col = hh * HDd + nf * 8 + (lane & 3) * 2;
        const size_t o0 = ((size_t)(bb * Ss) + srow0) * Hh + col;
        const size_t o1 = o0 + (size_t)8 * Hh;
        float v0 = O[nf][0] * inv0, v1 = O[nf][1] * inv0;
        float v2 = O[nf][2] * inv1, v3 = O[nf][3] * inv1;
        float h0 = __half2float(__float2half_rn(v0));
        float h1 = __half2float(__float2half_rn(v1));
        float h2 = __half2float(__float2half_rn(v2));
        float h3 = __half2float(__float2half_rn(v3));
        *(uint32_t*)&AOh[o0] = packh(v0, v1);
        *(uint32_t*)&AOl[o0] = packh(v0 - h0, v1 - h1);
        *(uint32_t*)&AOh[o1] = packh(v2, v3);
        *(uint32_t*)&AOl[o1] = packh(v2 - h2, v3 - h3);
    }
}

// ---------------------------------------------------------------------------
extern "C" void kernel_launch(void* const* d_in, const int* in_sizes, int n_in,
                              void* d_out, int out_size)
{
    (void)in_sizes; (void)n_in; (void)out_size;
    const float* x  = (const float*)d_in[0];
    const float* wq = (const float*)d_in[2];
    const float* bq = (const float*)d_in[3];
    const float* wk = (const float*)d_in[4];
    const float* bk = (const float*)d_in[5];
    const float* wv = (const float*)d_in[6];
    const float* bv = (const float*)d_in[7];
    const float* wo = (const float*)d_in[8];
    const float* bo = (const float*)d_in[9];
    float* out = (float*)d_out;

    __half *xh, *xl, *qh, *ql, *ks, *vs, *aoh, *aol, *wt;
    cudaGetSymbolAddress((void**)&xh,  g_Xh);
    cudaGetSymbolAddress((void**)&xl,  g_Xl);
    cudaGetSymbolAddress((void**)&qh,  g_Qh);
    cudaGetSymbolAddress((void**)&ql,  g_Ql);
    cudaGetSymbolAddress((void**)&ks,  g_Ks);
    cudaGetSymbolAddress((void**)&vs,  g_Vs);
    cudaGetSymbolAddress((void**)&aoh, g_AOh);
    cudaGetSymbolAddress((void**)&aol, g_AOl);
    cudaGetSymbolAddress((void**)&wt,  g_Wt);
    const size_t WSZ = (size_t)Hh * Hh;

    static bool attr_set = false;
    if (!attr_set) {
        cudaFuncSetAttribute(gemm_mma<0>,
                             cudaFuncAttributeMaxDynamicSharedMemorySize, GEMM_SMEM_BYTES);
        cudaFuncSetAttribute(gemm_mma<1>,
                             cudaFuncAttributeMaxDynamicSharedMemorySize, GEMM_SMEM_BYTES);
        cudaFuncSetAttribute(gemm_mma<2>,
                             cudaFuncAttributeMaxDynamicSharedMemorySize, GEMM_SMEM_BYTES);
        cudaFuncSetAttribute(attn_mma,
                             cudaFuncAttributeMaxDynamicSharedMemorySize, ATT2_SMEM);
        attr_set = true;
    }

    const int N2 = Mm * Hh / 2;
    convert_split<<<(N2 + 255) / 256, 256>>>(
        (const float2*)x, (__half2*)xh, (__half2*)xl, N2);

    dim3 tg(Hh / 32, Hh / 32), tb(32, 8);
    transpose_convert<<<tg, tb>>>(wq, wt + 0 * WSZ);
    transpose_convert<<<tg, tb>>>(wk, wt + 1 * WSZ);
    transpose_convert<<<tg, tb>>>(wv, wt + 2 * WSZ);
    transpose_convert<<<tg, tb>>>(wo, wt + 3 * WSZ);

    dim3 gg(Hh / 128, Mm / 128);
    gemm_mma<1><<<gg, 256, GEMM_SMEM_BYTES>>>(xh, xl, wt + 0 * WSZ, bq,
                                              nullptr, qh, ql);
    gemm_mma<2><<<gg, 256, GEMM_SMEM_BYTES>>>(xh, xl, wt + 1 * WSZ, bk,
                                              nullptr, ks, nullptr);
    gemm_mma<2><<<gg, 256, GEMM_SMEM_BYTES>>>(xh, xl, wt + 2 * WSZ, bv,
                                              nullptr, vs, nullptr);

    attn_mma<<<dim3(Ss / AQT, NHh, Bb), 256, ATT2_SMEM>>>(qh, ql, ks, vs,
                                                          aoh, aol);

    gemm_mma<0><<<gg, 256, GEMM_SMEM_BYTES>>>(aoh, aol, wt + 3 * WSZ, bo,
                                              out, nullptr, nullptr);
}

// round 6
// speedup vs baseline: 4.5379x; 1.2050x over previous
#include <cuda_runtime.h>
#include <cuda_fp16.h>
#include <cstdint>

// Problem constants
#define Bb   2
#define Ss   2048
#define Hh   2048
#define NHh  16
#define HDd  128
#define Mm   4096   // B*S

// ---------------------------------------------------------------------------
// Scratch (device globals; no allocation allowed)
// ---------------------------------------------------------------------------
__device__ __half g_Xh[(size_t)Mm * Hh];
__device__ __half g_Xl[(size_t)Mm * Hh];
__device__ __half g_Qh[(size_t)Mm * Hh];
__device__ __half g_Ql[(size_t)Mm * Hh];
__device__ __half g_Ks[(size_t)Mm * Hh];
__device__ __half g_Vs[(size_t)Mm * Hh];
__device__ __half g_AOh[(size_t)Mm * Hh];
__device__ __half g_Wt[4][(size_t)Hh * Hh];

// ---------------------------------------------------------------------------
// PTX helpers (sm_80-level only: legal in compute_103 PTX)
// ---------------------------------------------------------------------------
__device__ __forceinline__ uint32_t smem_to_u32(const void* p) {
    uint32_t a;
    asm("{ .reg .u64 t; cvta.to.shared.u64 t, %1; cvt.u32.u64 %0, t; }"
        : "=r"(a) : "l"(p));
    return a;
}
__device__ __forceinline__ void cp16(uint32_t s, const void* g) {
    asm volatile("cp.async.cg.shared.global [%0], [%1], 16;" :: "r"(s), "l"(g));
}
#define CP_COMMIT() asm volatile("cp.async.commit_group;" ::: "memory")
#define CP_WAIT0()  asm volatile("cp.async.wait_group 0;" ::: "memory")
#define CP_WAIT1()  asm volatile("cp.async.wait_group 1;" ::: "memory")

__device__ __forceinline__ void ldm_x4(uint32_t& r0, uint32_t& r1, uint32_t& r2,
                                       uint32_t& r3, uint32_t addr) {
    asm volatile("ldmatrix.sync.aligned.m8n8.x4.shared.b16 {%0,%1,%2,%3}, [%4];"
                 : "=r"(r0), "=r"(r1), "=r"(r2), "=r"(r3) : "r"(addr));
}
__device__ __forceinline__ void ldm_x4t(uint32_t& r0, uint32_t& r1, uint32_t& r2,
                                        uint32_t& r3, uint32_t addr) {
    asm volatile("ldmatrix.sync.aligned.m8n8.x4.trans.shared.b16 {%0,%1,%2,%3}, [%4];"
                 : "=r"(r0), "=r"(r1), "=r"(r2), "=r"(r3) : "r"(addr));
}
__device__ __forceinline__ void ldm_x2(uint32_t& r0, uint32_t& r1, uint32_t addr) {
    asm volatile("ldmatrix.sync.aligned.m8n8.x2.shared.b16 {%0,%1}, [%2];"
                 : "=r"(r0), "=r"(r1) : "r"(addr));
}
__device__ __forceinline__ void mma_f16(float* c, const uint32_t* a, const uint32_t* b) {
    asm volatile("mma.sync.aligned.m16n8k16.row.col.f32.f16.f16.f32 "
                 "{%0,%1,%2,%3}, {%4,%5,%6,%7}, {%8,%9}, {%0,%1,%2,%3};"
                 : "+f"(c[0]), "+f"(c[1]), "+f"(c[2]), "+f"(c[3])
                 : "r"(a[0]), "r"(a[1]), "r"(a[2]), "r"(a[3]), "r"(b[0]), "r"(b[1]));
}

// Fast exp2 on the FMA pipe (deg-5 poly, f in [-0.5,0.5]); rel err ~2.4e-6.
__device__ __forceinline__ float exp2p(float t) {
    t = fmaxf(t, -120.f);
    float fn = t + 12582912.f;
    int   n  = __float_as_int(fn) - 0x4B400000;
    float f  = t - (fn - 12582912.f);
    float p  = 1.3333558146428443e-3f;
    p = fmaf(p, f, 9.6181291076284772e-3f);
    p = fmaf(p, f, 5.5504108664821580e-2f);
    p = fmaf(p, f, 2.4022650695910071e-1f);
    p = fmaf(p, f, 6.9314718055994531e-1f);
    p = fmaf(p, f, 1.0f);
    return p * __int_as_float((n + 127) << 23);
}

__device__ __forceinline__ uint32_t packh(float x, float y) {
    __half2 t = __floats2half2_rn(x, y);
    return *reinterpret_cast<uint32_t*>(&t);
}

// ---------------------------------------------------------------------------
// Conversions
// ---------------------------------------------------------------------------
__global__ void convert_split(const float2* __restrict__ X,
                              __half2* __restrict__ Xh,
                              __half2* __restrict__ Xl, int n2)
{
    int i = blockIdx.x * blockDim.x + threadIdx.x;
    if (i >= n2) return;
    float2 v = X[i];
    __half h0 = __float2half_rn(v.x);
    __half h1 = __float2half_rn(v.y);
    float r0 = v.x - __half2float(h0);
    float r1 = v.y - __half2float(h1);
    Xh[i] = __half2(h0, h1);
    Xl[i] = __half2(__float2half_rn(r0), __float2half_rn(r1));
}

// Fused transpose + convert for all 4 weights (z selects the matrix)
__global__ void transpose_convert4(const float* __restrict__ w0,
                                   const float* __restrict__ w1,
                                   const float* __restrict__ w2,
                                   const float* __restrict__ w3,
                                   __half* __restrict__ T)
{
    __shared__ float t[32][33];
    const float* W = (blockIdx.z == 0) ? w0 : (blockIdx.z == 1) ? w1
                   : (blockIdx.z == 2) ? w2 : w3;
    __half* Td = T + (size_t)blockIdx.z * Hh * Hh;
    const int n0 = blockIdx.x * 32, k0 = blockIdx.y * 32;
    const int tx = threadIdx.x, ty = threadIdx.y;   // (32, 8)
#pragma unroll
    for (int i = 0; i < 4; i++)
        t[ty + 8 * i][tx] = W[(size_t)(k0 + ty + 8 * i) * Hh + n0 + tx];
    __syncthreads();
#pragma unroll
    for (int i = 0; i < 4; i++)
        Td[(size_t)(n0 + ty + 8 * i) * Hh + k0 + tx] =
            __float2half_rn(t[tx][ty + 8 * i]);
}

// ---------------------------------------------------------------------------
// HMMA fp16 GEMM. ASPLIT=1: C = (Ah+Al) @ B^T + bias (2 MMAs);
// ASPLIT=0: C = Ah @ B^T + bias (1 MMA).
// CTA 128x128, BK=32, 8 warps (warp tile 64x32), 3-stage cp.async pipeline.
// MODE 0: fp32 row-major.  MODE 1: fp16 hi/lo head-major.  MODE 2: fp16 head-major.
// ---------------------------------------------------------------------------
#define BKg   32
#define PADR  40
#define TILE_HALFS (128 * PADR)
#define TILE_B ((uint32_t)(TILE_HALFS * 2))

template <int ASPLIT>
__device__ __forceinline__ void stage_load(uint32_t sb,
    const __half* __restrict__ Ah, const __half* __restrict__ Al,
    const __half* __restrict__ Bs, int bm, int bn, int k0, int tid)
{
    const int r = tid >> 1;
    const int c = (tid & 1) * 2;
#pragma unroll
    for (int cc = 0; cc < 2; cc++) {
        const uint32_t so = (uint32_t)(r * PADR + (c + cc) * 8) * 2;
        const size_t go = (size_t)k0 + (c + cc) * 8;
        cp16(sb + so, Ah + (size_t)(bm + r) * Hh + go);
        if (ASPLIT)
            cp16(sb + TILE_B + so, Al + (size_t)(bm + r) * Hh + go);
        cp16(sb + (ASPLIT ? 2 : 1) * TILE_B + so,
             Bs + (size_t)(bn + r) * Hh + go);
    }
}

template <int MODE, int ASPLIT>
__global__ __launch_bounds__(256, 1)
void gemm_mma(const __half* __restrict__ Ah, const __half* __restrict__ Al,
              const __half* __restrict__ Bs, const float* __restrict__ bias,
              float* __restrict__ Cf, __half* __restrict__ Ch,
              __half* __restrict__ Cl)
{
    const uint32_t STAGE_B = (ASPLIT ? 3u : 2u) * TILE_B;
    extern __shared__ __half smem[];
    const uint32_t sbase = smem_to_u32(smem);
    const int tid = threadIdx.x;
    const int wid = tid >> 5, lane = tid & 31;
    const int bn = blockIdx.x * 128, bm = blockIdx.y * 128;
    const int wm = (wid >> 2) * 64;
    const int wn = (wid & 3) * 32;

    float acc[4][4][4];
#pragma unroll
    for (int i = 0; i < 4; i++)
#pragma unroll
        for (int j = 0; j < 4; j++)
#pragma unroll
            for (int q = 0; q < 4; q++) acc[i][j][q] = 0.f;

    const int NIT = Hh / BKg;   // 64
    stage_load<ASPLIT>(sbase, Ah, Al, Bs, bm, bn, 0, tid);
    CP_COMMIT();
    stage_load<ASPLIT>(sbase + STAGE_B, Ah, Al, Bs, bm, bn, BKg, tid);
    CP_COMMIT();
    CP_WAIT1();
    __syncthreads();

    const int arow = lane & 15;
    const int acol8 = (lane >> 4) << 3;
    const int brow = lane & 7;
    const int bcol8 = ((lane >> 3) & 1) << 3;

    for (int kt = 0; kt < NIT; kt++) {
        const uint32_t sb = sbase + (uint32_t)(kt % 3) * STAGE_B;
        if (kt + 2 < NIT) {
            stage_load<ASPLIT>(sbase + (uint32_t)((kt + 2) % 3) * STAGE_B,
                               Ah, Al, Bs, bm, bn, (kt + 2) * BKg, tid);
            CP_COMMIT();
        }

#pragma unroll
        for (int ks = 0; ks < 2; ks++) {
            const int k0 = ks * 16;
            uint32_t aH[4][4], aL[4][4], bF[4][2];
#pragma unroll
            for (int mi = 0; mi < 4; mi++) {
                const uint32_t off =
                    (uint32_t)((wm + mi * 16 + arow) * PADR + k0 + acol8) * 2;
                ldm_x4(aH[mi][0], aH[mi][1], aH[mi][2], aH[mi][3], sb + off);
                if (ASPLIT)
                    ldm_x4(aL[mi][0], aL[mi][1], aL[mi][2], aL[mi][3],
                           sb + TILE_B + off);
            }
#pragma unroll
            for (int ni = 0; ni < 4; ni++) {
                const uint32_t off =
                    (uint32_t)((wn + ni * 8 + brow) * PADR + k0 + bcol8) * 2;
                ldm_x2(bF[ni][0], bF[ni][1],
                       sb + (ASPLIT ? 2 : 1) * TILE_B + off);
            }
#pragma unroll
            for (int mi = 0; mi < 4; mi++)
#pragma unroll
                for (int ni = 0; ni < 4; ni++) {
                    mma_f16(acc[mi][ni], aH[mi], bF[ni]);
                    if (ASPLIT) mma_f16(acc[mi][ni], aL[mi], bF[ni]);
                }
        }

        if (kt + 1 < NIT) {
            if (kt + 2 < NIT) { CP_WAIT1(); } else { CP_WAIT0(); }
        }
        __syncthreads();
    }

    const int fr = lane >> 2;
    const int fc = (lane & 3) * 2;
#pragma unroll
    for (int mi = 0; mi < 4; mi++) {
#pragma unroll
        for (int ni = 0; ni < 4; ni++) {
            const int n0 = bn + wn + ni * 8 + fc;
            const float b0 = bias[n0], b1 = bias[n0 + 1];
#pragma unroll
            for (int half = 0; half < 2; half++) {
                const int m = bm + wm + mi * 16 + fr + half * 8;
                float v0 = acc[mi][ni][half * 2 + 0] + b0;
                float v1 = acc[mi][ni][half * 2 + 1] + b1;
                if (MODE == 0) {
                    float2 w; w.x = v0; w.y = v1;
                    *(float2*)&Cf[(size_t)m * Hh + n0] = w;
                } else {
                    const int bb = m >> 11;
                    const int ss = m & (Ss - 1);
                    const int hh = n0 >> 7;
                    const int dd = n0 & (HDd - 1);
                    const size_t idx =
                        (((size_t)(bb * NHh + hh) * Ss) + ss) * HDd + dd;
                    if (MODE == 1) {
                        __half h0 = __float2half_rn(v0);
                        __half h1 = __float2half_rn(v1);
                        float r0 = v0 - __half2float(h0);
                        float r1 = v1 - __half2float(h1);
                        *(__half2*)&Ch[idx] = __half2(h0, h1);
                        *(__half2*)&Cl[idx] = __half2(
                            __float2half_rn(r0), __float2half_rn(r1));
                    } else {
                        *(__half2*)&Ch[idx] = __floats2half2_rn(v0, v1);
                    }
                }
            }
        }
    }
}

#define GEMM_SMEM_SPLIT  (3 * 3 * (int)TILE_B)
#define GEMM_SMEM_SINGLE (3 * 2 * (int)TILE_B)

// ---------------------------------------------------------------------------
// HMMA fp16 flash attention: Q split (2-MMA scores), K/V single, P single PV.
// CTA: 128 q rows, 8 warps x 16 rows. KT=64, double-buffered cp.async.
// ---------------------------------------------------------------------------
#define AQT 128
#define AKT 64
#define PADV 136
#define KV_TILE_B  (AKT * PADV * 2)        // 17408 bytes
#define KV_STAGE_B (2 * KV_TILE_B)         // K, V = 34816 bytes
#define ATT2_SMEM  (2 * KV_STAGE_B)        // 69632 bytes

__device__ __forceinline__ void stage_kv(uint32_t dst, size_t base, int kn0,
    const __half* __restrict__ Ks, const __half* __restrict__ Vs, int tid)
{
#pragma unroll
    for (int i = 0; i < 4; i++) {
        const int idx = i * 256 + tid;
        const int row = idx >> 4, ch = idx & 15;
        const uint32_t so = (uint32_t)(row * PADV + ch * 8) * 2;
        const size_t go = base + (size_t)(kn0 + row) * HDd + ch * 8;
        cp16(dst +             so, Ks + go);
        cp16(dst + KV_TILE_B + so, Vs + go);
    }
}

__global__ __launch_bounds__(256, 1)
void attn_mma(const __half* __restrict__ Qh, const __half* __restrict__ Ql,
              const __half* __restrict__ Ks, const __half* __restrict__ Vs,
              __half* __restrict__ AOh)
{
    extern __shared__ __half asmem[];
    const uint32_t sb = smem_to_u32(asmem);
    const int tid = threadIdx.x, wid = tid >> 5, lane = tid & 31;
    const int qi = (int)gridDim.x - 1 - (int)blockIdx.x;   // big tiles first
    const int hh = blockIdx.y, bb = blockIdx.z;
    const size_t base = ((size_t)(bb * NHh + hh)) * Ss * HDd;
    const int q0 = qi * AQT;
    const float Cs = 0.12751745210319466f;   // 128^-0.5 * log2(e)

    // ---- load Q hi/lo fragments (staged through smem) ----
    uint32_t qfh[8][4], qfl[8][4];
    {
        const int qrow = wid * 16 + (lane & 15);
        const int qc8 = (lane >> 4) << 3;
#pragma unroll
        for (int i = 0; i < 8; i++) {
            const int idx = i * 256 + tid;
            const int row = idx >> 4, ch = idx & 15;
            cp16(sb + (uint32_t)(row * PADV + ch * 8) * 2,
                 Qh + base + (size_t)(q0 + row) * HDd + ch * 8);
        }
        CP_COMMIT(); CP_WAIT0(); __syncthreads();
#pragma unroll
        for (int kk = 0; kk < 8; kk++)
            ldm_x4(qfh[kk][0], qfh[kk][1], qfh[kk][2], qfh[kk][3],
                   sb + (uint32_t)(qrow * PADV + kk * 16 + qc8) * 2);
        __syncthreads();
#pragma unroll
        for (int i = 0; i < 8; i++) {
            const int idx = i * 256 + tid;
            const int row = idx >> 4, ch = idx & 15;
            cp16(sb + (uint32_t)(row * PADV + ch * 8) * 2,
                 Ql + base + (size_t)(q0 + row) * HDd + ch * 8);
        }
        CP_COMMIT(); CP_WAIT0(); __syncthreads();
#pragma unroll
        for (int kk = 0; kk < 8; kk++)
            ldm_x4(qfl[kk][0], qfl[kk][1], qfl[kk][2], qfl[kk][3],
                   sb + (uint32_t)(qrow * PADV + kk * 16 + qc8) * 2);
        __syncthreads();
    }

    float O[16][4];
#pragma unroll
    for (int i = 0; i < 16; i++)
#pragma unroll
        for (int j = 0; j < 4; j++) O[i][j] = 0.f;
    float m0 = -1e30f, m1 = -1e30f, l0 = 0.f, l1 = 0.f;

    const int nkt = 2 * qi + 2;
    stage_kv(sb, base, 0, Ks, Vs, tid);
    CP_COMMIT();

    for (int kt = 0; kt < nkt; kt++) {
        const uint32_t cur = sb + (uint32_t)((kt & 1) * KV_STAGE_B);
        if (kt + 1 < nkt) {
            stage_kv(sb + (uint32_t)(((kt + 1) & 1) * KV_STAGE_B), base,
                     (kt + 1) * AKT, Ks, Vs, tid);
            CP_COMMIT();
            CP_WAIT1();
        } else {
            CP_WAIT0();
        }
        __syncthreads();

        const uint32_t KsS = cur, VsS = cur + KV_TILE_B;

        // ---- scores ----
        float c[8][4];
#pragma unroll
        for (int i = 0; i < 8; i++)
#pragma unroll
            for (int j = 0; j < 4; j++) c[i][j] = 0.f;

#pragma unroll
        for (int kk = 0; kk < 8; kk++) {
            const uint32_t kc = (uint32_t)(kk * 16 + ((lane >> 3) & 1) * 8) * 2;
#pragma unroll
            for (int nfp = 0; nfp < 4; nfp++) {
                const uint32_t nrow =
                    (uint32_t)(nfp * 16 + ((lane >> 4) << 3) + (lane & 7));
                uint32_t h0, h1, h2, h3;
                ldm_x4(h0, h1, h2, h3, KsS + nrow * (PADV * 2) + kc);
                uint32_t bA[2] = {h0, h1}, bB[2] = {h2, h3};
                mma_f16(c[2 * nfp],     qfh[kk], bA);
                mma_f16(c[2 * nfp],     qfl[kk], bA);
                mma_f16(c[2 * nfp + 1], qfh[kk], bB);
                mma_f16(c[2 * nfp + 1], qfl[kk], bB);
            }
        }

        // ---- causal mask ----
        const int kn0 = kt * AKT;
        if (kn0 + AKT - 1 > q0 + wid * 16) {
            const int row0 = q0 + wid * 16 + (lane >> 2);
            const int col0 = kn0 + (lane & 3) * 2;
#pragma unroll
            for (int nf = 0; nf < 8; nf++) {
                const int cb = col0 + nf * 8;
                if (cb     > row0)     c[nf][0] = -1e30f;
                if (cb + 1 > row0)     c[nf][1] = -1e30f;
                if (cb     > row0 + 8) c[nf][2] = -1e30f;
                if (cb + 1 > row0 + 8) c[nf][3] = -1e30f;
            }
        }

        // ---- online softmax ----
        float rm0 = -1e30f, rm1 = -1e30f;
#pragma unroll
        for (int nf = 0; nf < 8; nf++) {
            rm0 = fmaxf(rm0, fmaxf(c[nf][0], c[nf][1]));
            rm1 = fmaxf(rm1, fmaxf(c[nf][2], c[nf][3]));
        }
        rm0 = fmaxf(rm0, __shfl_xor_sync(0xffffffffu, rm0, 1));
        rm0 = fmaxf(rm0, __shfl_xor_sync(0xffffffffu, rm0, 2));
        rm1 = fmaxf(rm1, __shfl_xor_sync(0xffffffffu, rm1, 1));
        rm1 = fmaxf(rm1, __shfl_xor_sync(0xffffffffu, rm1, 2));
        const float mn0 = fmaxf(m0, rm0), mn1 = fmaxf(m1, rm1);
        const float a0 = exp2p((m0 - mn0) * Cs);
        const float a1 = exp2p((m1 - mn1) * Cs);
        m0 = mn0; m1 = mn1;

        float rs0 = 0.f, rs1 = 0.f;
#pragma unroll
        for (int nf = 0; nf < 8; nf++) {
            c[nf][0] = exp2p((c[nf][0] - mn0) * Cs);
            c[nf][1] = exp2p((c[nf][1] - mn0) * Cs);
            c[nf][2] = exp2p((c[nf][2] - mn1) * Cs);
            c[nf][3] = exp2p((c[nf][3] - mn1) * Cs);
            rs0 += c[nf][0] + c[nf][1];
            rs1 += c[nf][2] + c[nf][3];
        }
        rs0 += __shfl_xor_sync(0xffffffffu, rs0, 1);
        rs0 += __shfl_xor_sync(0xffffffffu, rs0, 2);
        rs1 += __shfl_xor_sync(0xffffffffu, rs1, 1);
        rs1 += __shfl_xor_sync(0xffffffffu, rs1, 2);
        l0 = l0 * a0 + rs0;
        l1 = l1 * a1 + rs1;

#pragma unroll
        for (int i = 0; i < 16; i++) {
            O[i][0] *= a0; O[i][1] *= a0; O[i][2] *= a1; O[i][3] *= a1;
        }

        // ---- pack P fragments (single fp16) ----
        uint32_t pah[4][4];
#pragma unroll
        for (int k2 = 0; k2 < 4; k2++) {
#pragma unroll
            for (int q = 0; q < 4; q++) {
                const int nf = 2 * k2 + (q >> 1);
                const int e  = (q & 1) * 2;
                pah[k2][q] = packh(c[nf][e], c[nf][e + 1]);
            }
        }

        // ---- O += P @ V ----
#pragma unroll
        for (int k2 = 0; k2 < 4; k2++) {
            const uint32_t vr =
                (uint32_t)(k2 * 16 + (lane & 7) + ((lane >> 3) & 1) * 8);
#pragma unroll
            for (int nfp = 0; nfp < 8; nfp++) {
                const uint32_t vc = (uint32_t)(nfp * 16 + ((lane >> 4) << 3));
                uint32_t h0, h1, h2, h3;
                ldm_x4t(h0, h1, h2, h3, VsS + (vr * PADV + vc) * 2);
                uint32_t bA[2] = {h0, h1}, bB[2] = {h2, h3};
                mma_f16(O[2 * nfp],     pah[k2], bA);
                mma_f16(O[2 * nfp + 1], pah[k2], bB);
            }
        }
        __syncthreads();
    }

    // ---- epilogue: normalize, write AO single fp16 [B,S,H] ----
    const float inv0 = 1.f / l0, inv1 = 1.f / l1;
    const int srow0 = q0 + wid * 16 + (lane >> 2);
#pragma unroll
    for (int nf = 0; nf < 16; nf++) {
        const int col = hh * HDd + nf * 8 + (lane & 3) * 2;
        const size_t o0 = ((size_t)(bb * Ss) + srow0) * Hh + col;
        const size_t o1 = o0 + (size_t)8 * Hh;
        *(uint32_t*)&AOh[o0] = packh(O[nf][0] * inv0, O[nf][1] * inv0);
        *(uint32_t*)&AOh[o1] = packh(O[nf][2] * inv1, O[nf][3] * inv1);
    }
}

// ---------------------------------------------------------------------------
extern "C" void kernel_launch(void* const* d_in, const int* in_sizes, int n_in,
                              void* d_out, int out_size)
{
    (void)in_sizes; (void)n_in; (void)out_size;
    const float* x  = (const float*)d_in[0];
    const float* wq = (const float*)d_in[2];
    const float* bq = (const float*)d_in[3];
    const float* wk = (const float*)d_in[4];
    const float* bk = (const float*)d_in[5];
    const float* wv = (const float*)d_in[6];
    const float* bv = (const float*)d_in[7];
    const float* wo = (const float*)d_in[8];
    const float* bo = (const float*)d_in[9];
    float* out = (float*)d_out;

    __half *xh, *xl, *qh, *ql, *ks, *vs, *aoh, *wt;
    cudaGetSymbolAddress((void**)&xh,  g_Xh);
    cudaGetSymbolAddress((void**)&xl,  g_Xl);
    cudaGetSymbolAddress((void**)&qh,  g_Qh);
    cudaGetSymbolAddress((void**)&ql,  g_Ql);
    cudaGetSymbolAddress((void**)&ks,  g_Ks);
    cudaGetSymbolAddress((void**)&vs,  g_Vs);
    cudaGetSymbolAddress((void**)&aoh, g_AOh);
    cudaGetSymbolAddress((void**)&wt,  g_Wt);
    const size_t WSZ = (size_t)Hh * Hh;

    static bool attr_set = false;
    if (!attr_set) {
        cudaFuncSetAttribute(gemm_mma<1, 1>,
                             cudaFuncAttributeMaxDynamicSharedMemorySize, GEMM_SMEM_SPLIT);
        cudaFuncSetAttribute(gemm_mma<2, 1>,
                             cudaFuncAttributeMaxDynamicSharedMemorySize, GEMM_SMEM_SPLIT);
        cudaFuncSetAttribute(gemm_mma<2, 0>,
                             cudaFuncAttributeMaxDynamicSharedMemorySize, GEMM_SMEM_SINGLE);
        cudaFuncSetAttribute(gemm_mma<0, 0>,
                             cudaFuncAttributeMaxDynamicSharedMemorySize, GEMM_SMEM_SINGLE);
        cudaFuncSetAttribute(attn_mma,
                             cudaFuncAttributeMaxDynamicSharedMemorySize, ATT2_SMEM);
        attr_set = true;
    }

    const int N2 = Mm * Hh / 2;
    convert_split<<<(N2 + 255) / 256, 256>>>(
        (const float2*)x, (__half2*)xh, (__half2*)xl, N2);

    transpose_convert4<<<dim3(Hh / 32, Hh / 32, 4), dim3(32, 8)>>>(
        wq, wk, wv, wo, wt);

    dim3 gg(Hh / 128, Mm / 128);
    // Q: x split (exp-amplified path), hi/lo out
    gemm_mma<1, 1><<<gg, 256, GEMM_SMEM_SPLIT>>>(xh, xl, wt + 0 * WSZ, bq,
                                                 nullptr, qh, ql);
    // K: x split (exp-amplified path), single out
    gemm_mma<2, 1><<<gg, 256, GEMM_SMEM_SPLIT>>>(xh, xl, wt + 1 * WSZ, bk,
                                                 nullptr, ks, nullptr);
    // V: x single (linear path), single out
    gemm_mma<2, 0><<<gg, 256, GEMM_SMEM_SINGLE>>>(xh, nullptr, wt + 2 * WSZ, bv,
                                                  nullptr, vs, nullptr);

    attn_mma<<<dim3(Ss / AQT, NHh, Bb), 256, ATT2_SMEM>>>(qh, ql, ks, vs, aoh);

    // Output projection: AO single (linear path), fp32 out
    gemm_mma<0, 0><<<gg, 256, GEMM_SMEM_SINGLE>>>(aoh, nullptr, wt + 3 * WSZ, bo,
                                                  out, nullptr, nullptr);
}

// round 7
// speedup vs baseline: 5.2392x; 1.1545x over previous
#include <cuda_runtime.h>
#include <cuda_fp16.h>
#include <cstdint>

// Problem constants
#define Bb   2
#define Ss   2048
#define Hh   2048
#define NHh  16
#define HDd  128
#define Mm   4096   // B*S

// ---------------------------------------------------------------------------
// Scratch (device globals; no allocation allowed)
// ---------------------------------------------------------------------------
__device__ __half g_Xh[(size_t)Mm * Hh];
__device__ __half g_Xl[(size_t)Mm * Hh];
__device__ __half g_Qh[(size_t)Mm * Hh];
__device__ __half g_Ql[(size_t)Mm * Hh];
__device__ __half g_Ks[(size_t)Mm * Hh];
__device__ __half g_Vs[(size_t)Mm * Hh];
__device__ __half g_AOh[(size_t)Mm * Hh];
__device__ __half g_Wt[4][(size_t)Hh * Hh];

// ---------------------------------------------------------------------------
// PTX helpers (sm_80-level only: legal in compute_103 PTX)
// ---------------------------------------------------------------------------
__device__ __forceinline__ uint32_t smem_to_u32(const void* p) {
    uint32_t a;
    asm("{ .reg .u64 t; cvta.to.shared.u64 t, %1; cvt.u32.u64 %0, t; }"
        : "=r"(a) : "l"(p));
    return a;
}
__device__ __forceinline__ void cp16(uint32_t s, const void* g) {
    asm volatile("cp.async.cg.shared.global [%0], [%1], 16;" :: "r"(s), "l"(g));
}
#define CP_COMMIT() asm volatile("cp.async.commit_group;" ::: "memory")
#define CP_WAIT0()  asm volatile("cp.async.wait_group 0;" ::: "memory")
#define CP_WAIT1()  asm volatile("cp.async.wait_group 1;" ::: "memory")

__device__ __forceinline__ void ldm_x4(uint32_t& r0, uint32_t& r1, uint32_t& r2,
                                       uint32_t& r3, uint32_t addr) {
    asm volatile("ldmatrix.sync.aligned.m8n8.x4.shared.b16 {%0,%1,%2,%3}, [%4];"
                 : "=r"(r0), "=r"(r1), "=r"(r2), "=r"(r3) : "r"(addr));
}
__device__ __forceinline__ void ldm_x4t(uint32_t& r0, uint32_t& r1, uint32_t& r2,
                                        uint32_t& r3, uint32_t addr) {
    asm volatile("ldmatrix.sync.aligned.m8n8.x4.trans.shared.b16 {%0,%1,%2,%3}, [%4];"
                 : "=r"(r0), "=r"(r1), "=r"(r2), "=r"(r3) : "r"(addr));
}
__device__ __forceinline__ void ldm_x2(uint32_t& r0, uint32_t& r1, uint32_t addr) {
    asm volatile("ldmatrix.sync.aligned.m8n8.x2.shared.b16 {%0,%1}, [%2];"
                 : "=r"(r0), "=r"(r1) : "r"(addr));
}
__device__ __forceinline__ void mma_f16(float* c, const uint32_t* a, const uint32_t* b) {
    asm volatile("mma.sync.aligned.m16n8k16.row.col.f32.f16.f16.f32 "
                 "{%0,%1,%2,%3}, {%4,%5,%6,%7}, {%8,%9}, {%0,%1,%2,%3};"
                 : "+f"(c[0]), "+f"(c[1]), "+f"(c[2]), "+f"(c[3])
                 : "r"(a[0]), "r"(a[1]), "r"(a[2]), "r"(a[3]), "r"(b[0]), "r"(b[1]));
}

// Fast exp2 on the FMA pipe (deg-5 poly, f in [-0.5,0.5]); rel err ~2.4e-6.
__device__ __forceinline__ float exp2p(float t) {
    t = fmaxf(t, -120.f);
    float fn = t + 12582912.f;
    int   n  = __float_as_int(fn) - 0x4B400000;
    float f  = t - (fn - 12582912.f);
    float p  = 1.3333558146428443e-3f;
    p = fmaf(p, f, 9.6181291076284772e-3f);
    p = fmaf(p, f, 5.5504108664821580e-2f);
    p = fmaf(p, f, 2.4022650695910071e-1f);
    p = fmaf(p, f, 6.9314718055994531e-1f);
    p = fmaf(p, f, 1.0f);
    return p * __int_as_float((n + 127) << 23);
}

__device__ __forceinline__ uint32_t packh(float x, float y) {
    __half2 t = __floats2half2_rn(x, y);
    return *reinterpret_cast<uint32_t*>(&t);
}

// ---------------------------------------------------------------------------
// Conversions
// ---------------------------------------------------------------------------
__global__ void convert_split(const float2* __restrict__ X,
                              __half2* __restrict__ Xh,
                              __half2* __restrict__ Xl, int n2)
{
    int i = blockIdx.x * blockDim.x + threadIdx.x;
    if (i >= n2) return;
    float2 v = X[i];
    __half h0 = __float2half_rn(v.x);
    __half h1 = __float2half_rn(v.y);
    float r0 = v.x - __half2float(h0);
    float r1 = v.y - __half2float(h1);
    Xh[i] = __half2(h0, h1);
    Xl[i] = __half2(__float2half_rn(r0), __float2half_rn(r1));
}

// Fused transpose + convert for all 4 weights (z selects the matrix)
__global__ void transpose_convert4(const float* __restrict__ w0,
                                   const float* __restrict__ w1,
                                   const float* __restrict__ w2,
                                   const float* __restrict__ w3,
                                   __half* __restrict__ T)
{
    __shared__ float t[32][33];
    const float* W = (blockIdx.z == 0) ? w0 : (blockIdx.z == 1) ? w1
                   : (blockIdx.z == 2) ? w2 : w3;
    __half* Td = T + (size_t)blockIdx.z * Hh * Hh;
    const int n0 = blockIdx.x * 32, k0 = blockIdx.y * 32;
    const int tx = threadIdx.x, ty = threadIdx.y;   // (32, 8)
#pragma unroll
    for (int i = 0; i < 4; i++)
        t[ty + 8 * i][tx] = W[(size_t)(k0 + ty + 8 * i) * Hh + n0 + tx];
    __syncthreads();
#pragma unroll
    for (int i = 0; i < 4; i++)
        Td[(size_t)(n0 + ty + 8 * i) * Hh + k0 + tx] =
            __float2half_rn(t[tx][ty + 8 * i]);
}

// ---------------------------------------------------------------------------
// HMMA fp16 GEMM. ASPLIT=1: C = (Ah+Al) @ B^T + bias (2 MMAs);
// ASPLIT=0: C = Ah @ B^T + bias (1 MMA).
// CTA 128x128, BK=32, 8 warps (warp tile 64x32), 3-stage cp.async pipeline.
// 2 CTAs/SM (register-capped at 128): per-mi fragment loading keeps live regs low.
// MODE 0: fp32 row-major.  MODE 1: fp16 hi/lo head-major.  MODE 2: fp16 head-major.
// ---------------------------------------------------------------------------
#define BKg   32
#define PADR  40
#define TILE_HALFS (128 * PADR)
#define TILE_B ((uint32_t)(TILE_HALFS * 2))

template <int ASPLIT>
__device__ __forceinline__ void stage_load(uint32_t sb,
    const __half* __restrict__ Ah, const __half* __restrict__ Al,
    const __half* __restrict__ Bs, int bm, int bn, int k0, int tid)
{
    const int r = tid >> 1;
    const int c = (tid & 1) * 2;
#pragma unroll
    for (int cc = 0; cc < 2; cc++) {
        const uint32_t so = (uint32_t)(r * PADR + (c + cc) * 8) * 2;
        const size_t go = (size_t)k0 + (c + cc) * 8;
        cp16(sb + so, Ah + (size_t)(bm + r) * Hh + go);
        if (ASPLIT)
            cp16(sb + TILE_B + so, Al + (size_t)(bm + r) * Hh + go);
        cp16(sb + (ASPLIT ? 2 : 1) * TILE_B + so,
             Bs + (size_t)(bn + r) * Hh + go);
    }
}

template <int MODE, int ASPLIT>
__global__ __launch_bounds__(256, 2)
void gemm_mma(const __half* __restrict__ Ah, const __half* __restrict__ Al,
              const __half* __restrict__ Bs, const float* __restrict__ bias,
              float* __restrict__ Cf, __half* __restrict__ Ch,
              __half* __restrict__ Cl)
{
    const uint32_t STAGE_B = (ASPLIT ? 3u : 2u) * TILE_B;
    extern __shared__ __half smem[];
    const uint32_t sbase = smem_to_u32(smem);
    const int tid = threadIdx.x;
    const int wid = tid >> 5, lane = tid & 31;
    const int bn = blockIdx.x * 128, bm = blockIdx.y * 128;
    const int wm = (wid >> 2) * 64;
    const int wn = (wid & 3) * 32;

    float acc[4][4][4];
#pragma unroll
    for (int i = 0; i < 4; i++)
#pragma unroll
        for (int j = 0; j < 4; j++)
#pragma unroll
            for (int q = 0; q < 4; q++) acc[i][j][q] = 0.f;

    const int NIT = Hh / BKg;   // 64
    stage_load<ASPLIT>(sbase, Ah, Al, Bs, bm, bn, 0, tid);
    CP_COMMIT();
    stage_load<ASPLIT>(sbase + STAGE_B, Ah, Al, Bs, bm, bn, BKg, tid);
    CP_COMMIT();
    CP_WAIT1();
    __syncthreads();

    const int arow = lane & 15;
    const int acol8 = (lane >> 4) << 3;
    const int brow = lane & 7;
    const int bcol8 = ((lane >> 3) & 1) << 3;

    for (int kt = 0; kt < NIT; kt++) {
        const uint32_t sb = sbase + (uint32_t)(kt % 3) * STAGE_B;
        if (kt + 2 < NIT) {
            stage_load<ASPLIT>(sbase + (uint32_t)((kt + 2) % 3) * STAGE_B,
                               Ah, Al, Bs, bm, bn, (kt + 2) * BKg, tid);
            CP_COMMIT();
        }

#pragma unroll
        for (int ks = 0; ks < 2; ks++) {
            const int k0 = ks * 16;
            // B fragments for this k-slice (8 regs live)
            uint32_t bF[4][2];
#pragma unroll
            for (int ni = 0; ni < 4; ni++) {
                const uint32_t off =
                    (uint32_t)((wn + ni * 8 + brow) * PADR + k0 + bcol8) * 2;
                ldm_x2(bF[ni][0], bF[ni][1],
                       sb + (ASPLIT ? 2 : 1) * TILE_B + off);
            }
            // Per-mi A fragments (8 regs live) -> low register footprint
#pragma unroll
            for (int mi = 0; mi < 4; mi++) {
                const uint32_t off =
                    (uint32_t)((wm + mi * 16 + arow) * PADR + k0 + acol8) * 2;
                uint32_t aH[4];
                ldm_x4(aH[0], aH[1], aH[2], aH[3], sb + off);
#pragma unroll
                for (int ni = 0; ni < 4; ni++)
                    mma_f16(acc[mi][ni], aH, bF[ni]);
                if (ASPLIT) {
                    uint32_t aL[4];
                    ldm_x4(aL[0], aL[1], aL[2], aL[3], sb + TILE_B + off);
#pragma unroll
                    for (int ni = 0; ni < 4; ni++)
                        mma_f16(acc[mi][ni], aL, bF[ni]);
                }
            }
        }

        if (kt + 1 < NIT) {
            if (kt + 2 < NIT) { CP_WAIT1(); } else { CP_WAIT0(); }
        }
        __syncthreads();
    }

    const int fr = lane >> 2;
    const int fc = (lane & 3) * 2;
#pragma unroll
    for (int mi = 0; mi < 4; mi++) {
#pragma unroll
        for (int ni = 0; ni < 4; ni++) {
            const int n0 = bn + wn + ni * 8 + fc;
            const float b0 = bias[n0], b1 = bias[n0 + 1];
#pragma unroll
            for (int half = 0; half < 2; half++) {
                const int m = bm + wm + mi * 16 + fr + half * 8;
                float v0 = acc[mi][ni][half * 2 + 0] + b0;
                float v1 = acc[mi][ni][half * 2 + 1] + b1;
                if (MODE == 0) {
                    float2 w; w.x = v0; w.y = v1;
                    *(float2*)&Cf[(size_t)m * Hh + n0] = w;
                } else {
                    const int bb = m >> 11;
                    const int ss = m & (Ss - 1);
                    const int hh = n0 >> 7;
                    const int dd = n0 & (HDd - 1);
                    const size_t idx =
                        (((size_t)(bb * NHh + hh) * Ss) + ss) * HDd + dd;
                    if (MODE == 1) {
                        __half h0 = __float2half_rn(v0);
                        __half h1 = __float2half_rn(v1);
                        float r0 = v0 - __half2float(h0);
                        float r1 = v1 - __half2float(h1);
                        *(__half2*)&Ch[idx] = __half2(h0, h1);
                        *(__half2*)&Cl[idx] = __half2(
                            __float2half_rn(r0), __float2half_rn(r1));
                    } else {
                        *(__half2*)&Ch[idx] = __floats2half2_rn(v0, v1);
                    }
                }
            }
        }
    }
}

#define GEMM_SMEM_SPLIT  (3 * 3 * (int)TILE_B)
#define GEMM_SMEM_SINGLE (3 * 2 * (int)TILE_B)

// ---------------------------------------------------------------------------
// HMMA fp16 flash attention: Q split (2-MMA scores), K/V single, P single PV.
// CTA: 128 q rows, 8 warps x 16 rows. KT=64, double-buffered cp.async.
// ---------------------------------------------------------------------------
#define AQT 128
#define AKT 64
#define PADV 136
#define KV_TILE_B  (AKT * PADV * 2)        // 17408 bytes
#define KV_STAGE_B (2 * KV_TILE_B)         // K, V = 34816 bytes
#define ATT2_SMEM  (2 * KV_STAGE_B)        // 69632 bytes

__device__ __forceinline__ void stage_kv(uint32_t dst, size_t base, int kn0,
    const __half* __restrict__ Ks, const __half* __restrict__ Vs, int tid)
{
#pragma unroll
    for (int i = 0; i < 4; i++) {
        const int idx = i * 256 + tid;
        const int row = idx >> 4, ch = idx & 15;
        const uint32_t so = (uint32_t)(row * PADV + ch * 8) * 2;
        const size_t go = base + (size_t)(kn0 + row) * HDd + ch * 8;
        cp16(dst +             so, Ks + go);
        cp16(dst + KV_TILE_B + so, Vs + go);
    }
}

__global__ __launch_bounds__(256, 1)
void attn_mma(const __half* __restrict__ Qh, const __half* __restrict__ Ql,
              const __half* __restrict__ Ks, const __half* __restrict__ Vs,
              __half* __restrict__ AOh)
{
    extern __shared__ __half asmem[];
    const uint32_t sb = smem_to_u32(asmem);
    const int tid = threadIdx.x, wid = tid >> 5, lane = tid & 31;
    const int qi = (int)gridDim.x - 1 - (int)blockIdx.x;   // big tiles first
    const int hh = blockIdx.y, bb = blockIdx.z;
    const size_t base = ((size_t)(bb * NHh + hh)) * Ss * HDd;
    const int q0 = qi * AQT;
    const float Cs = 0.12751745210319466f;   // 128^-0.5 * log2(e)

    // ---- load Q hi/lo fragments (staged through smem) ----
    uint32_t qfh[8][4], qfl[8][4];
    {
        const int qrow = wid * 16 + (lane & 15);
        const int qc8 = (lane >> 4) << 3;
#pragma unroll
        for (int i = 0; i < 8; i++) {
            const int idx = i * 256 + tid;
            const int row = idx >> 4, ch = idx & 15;
            cp16(sb + (uint32_t)(row * PADV + ch * 8) * 2,
                 Qh + base + (size_t)(q0 + row) * HDd + ch * 8);
        }
        CP_COMMIT(); CP_WAIT0(); __syncthreads();
#pragma unroll
        for (int kk = 0; kk < 8; kk++)
            ldm_x4(qfh[kk][0], qfh[kk][1], qfh[kk][2], qfh[kk][3],
                   sb + (uint32_t)(qrow * PADV + kk * 16 + qc8) * 2);
        __syncthreads();
#pragma unroll
        for (int i = 0; i < 8; i++) {
            const int idx = i * 256 + tid;
            const int row = idx >> 4, ch = idx & 15;
            cp16(sb + (uint32_t)(row * PADV + ch * 8) * 2,
                 Ql + base + (size_t)(q0 + row) * HDd + ch * 8);
        }
        CP_COMMIT(); CP_WAIT0(); __syncthreads();
#pragma unroll
        for (int kk = 0; kk < 8; kk++)
            ldm_x4(qfl[kk][0], qfl[kk][1], qfl[kk][2], qfl[kk][3],
                   sb + (uint32_t)(qrow * PADV + kk * 16 + qc8) * 2);
        __syncthreads();
    }

    float O[16][4];
#pragma unroll
    for (int i = 0; i < 16; i++)
#pragma unroll
        for (int j = 0; j < 4; j++) O[i][j] = 0.f;
    float m0 = -1e30f, m1 = -1e30f, l0 = 0.f, l1 = 0.f;

    const int nkt = 2 * qi + 2;
    stage_kv(sb, base, 0, Ks, Vs, tid);
    CP_COMMIT();

    for (int kt = 0; kt < nkt; kt++) {
        const uint32_t cur = sb + (uint32_t)((kt & 1) * KV_STAGE_B);
        if (kt + 1 < nkt) {
            stage_kv(sb + (uint32_t)(((kt + 1) & 1) * KV_STAGE_B), base,
                     (kt + 1) * AKT, Ks, Vs, tid);
            CP_COMMIT();
            CP_WAIT1();
        } else {
            CP_WAIT0();
        }
        __syncthreads();

        const uint32_t KsS = cur, VsS = cur + KV_TILE_B;

        // ---- scores ----
        float c[8][4];
#pragma unroll
        for (int i = 0; i < 8; i++)
#pragma unroll
            for (int j = 0; j < 4; j++) c[i][j] = 0.f;

#pragma unroll
        for (int kk = 0; kk < 8; kk++) {
            const uint32_t kc = (uint32_t)(kk * 16 + ((lane >> 3) & 1) * 8) * 2;
#pragma unroll
            for (int nfp = 0; nfp < 4; nfp++) {
                const uint32_t nrow =
                    (uint32_t)(nfp * 16 + ((lane >> 4) << 3) + (lane & 7));
                uint32_t h0, h1, h2, h3;
                ldm_x4(h0, h1, h2, h3, KsS + nrow * (PADV * 2) + kc);
                uint32_t bA[2] = {h0, h1}, bB[2] = {h2, h3};
                mma_f16(c[2 * nfp],     qfh[kk], bA);
                mma_f16(c[2 * nfp],     qfl[kk], bA);
                mma_f16(c[2 * nfp + 1], qfh[kk], bB);
                mma_f16(c[2 * nfp + 1], qfl[kk], bB);
            }
        }

        // ---- causal mask ----
        const int kn0 = kt * AKT;
        if (kn0 + AKT - 1 > q0 + wid * 16) {
            const int row0 = q0 + wid * 16 + (lane >> 2);
            const int col0 = kn0 + (lane & 3) * 2;
#pragma unroll
            for (int nf = 0; nf < 8; nf++) {
                const int cb = col0 + nf * 8;
                if (cb     > row0)     c[nf][0] = -1e30f;
                if (cb + 1 > row0)     c[nf][1] = -1e30f;
                if (cb     > row0 + 8) c[nf][2] = -1e30f;
                if (cb + 1 > row0 + 8) c[nf][3] = -1e30f;
            }
        }

        // ---- online softmax ----
        float rm0 = -1e30f, rm1 = -1e30f;
#pragma unroll
        for (int nf = 0; nf < 8; nf++) {
            rm0 = fmaxf(rm0, fmaxf(c[nf][0], c[nf][1]));
            rm1 = fmaxf(rm1, fmaxf(c[nf][2], c[nf][3]));
        }
        rm0 = fmaxf(rm0, __shfl_xor_sync(0xffffffffu, rm0, 1));
        rm0 = fmaxf(rm0, __shfl_xor_sync(0xffffffffu, rm0, 2));
        rm1 = fmaxf(rm1, __shfl_xor_sync(0xffffffffu, rm1, 1));
        rm1 = fmaxf(rm1, __shfl_xor_sync(0xffffffffu, rm1, 2));
        const float mn0 = fmaxf(m0, rm0), mn1 = fmaxf(m1, rm1);
        const float a0 = exp2p((m0 - mn0) * Cs);
        const float a1 = exp2p((m1 - mn1) * Cs);
        m0 = mn0; m1 = mn1;

        float rs0 = 0.f, rs1 = 0.f;
#pragma unroll
        for (int nf = 0; nf < 8; nf++) {
            c[nf][0] = exp2p((c[nf][0] - mn0) * Cs);
            c[nf][1] = exp2p((c[nf][1] - mn0) * Cs);
            c[nf][2] = exp2p((c[nf][2] - mn1) * Cs);
            c[nf][3] = exp2p((c[nf][3] - mn1) * Cs);
            rs0 += c[nf][0] + c[nf][1];
            rs1 += c[nf][2] + c[nf][3];
        }
        rs0 += __shfl_xor_sync(0xffffffffu, rs0, 1);
        rs0 += __shfl_xor_sync(0xffffffffu, rs0, 2);
        rs1 += __shfl_xor_sync(0xffffffffu, rs1, 1);
        rs1 += __shfl_xor_sync(0xffffffffu, rs1, 2);
        l0 = l0 * a0 + rs0;
        l1 = l1 * a1 + rs1;

#pragma unroll
        for (int i = 0; i < 16; i++) {
            O[i][0] *= a0; O[i][1] *= a0; O[i][2] *= a1; O[i][3] *= a1;
        }

        // ---- pack P fragments (single fp16) ----
        uint32_t pah[4][4];
#pragma unroll
        for (int k2 = 0; k2 < 4; k2++) {
#pragma unroll
            for (int q = 0; q < 4; q++) {
                const int nf = 2 * k2 + (q >> 1);
                const int e  = (q & 1) * 2;
                pah[k2][q] = packh(c[nf][e], c[nf][e + 1]);
            }
        }

        // ---- O += P @ V ----
#pragma unroll
        for (int k2 = 0; k2 < 4; k2++) {
            const uint32_t vr =
                (uint32_t)(k2 * 16 + (lane & 7) + ((lane >> 3) & 1) * 8);
#pragma unroll
            for (int nfp = 0; nfp < 8; nfp++) {
                const uint32_t vc = (uint32_t)(nfp * 16 + ((lane >> 4) << 3));
                uint32_t h0, h1, h2, h3;
                ldm_x4t(h0, h1, h2, h3, VsS + (vr * PADV + vc) * 2);
                uint32_t bA[2] = {h0, h1}, bB[2] = {h2, h3};
                mma_f16(O[2 * nfp],     pah[k2], bA);
                mma_f16(O[2 * nfp + 1], pah[k2], bB);
            }
        }
        __syncthreads();
    }

    // ---- epilogue: normalize, write AO single fp16 [B,S,H] ----
    const float inv0 = 1.f / l0, inv1 = 1.f / l1;
    const int srow0 = q0 + wid * 16 + (lane >> 2);
#pragma unroll
    for (int nf = 0; nf < 16; nf++) {
        const int col = hh * HDd + nf * 8 + (lane & 3) * 2;
        const size_t o0 = ((size_t)(bb * Ss) + srow0) * Hh + col;
        const size_t o1 = o0 + (size_t)8 * Hh;
        *(uint32_t*)&AOh[o0] = packh(O[nf][0] * inv0, O[nf][1] * inv0);
        *(uint32_t*)&AOh[o1] = packh(O[nf][2] * inv1, O[nf][3] * inv1);
    }
}

// ---------------------------------------------------------------------------
extern "C" void kernel_launch(void* const* d_in, const int* in_sizes, int n_in,
                              void* d_out, int out_size)
{
    (void)in_sizes; (void)n_in; (void)out_size;
    const float* x  = (const float*)d_in[0];
    const float* wq = (const float*)d_in[2];
    const float* bq = (const float*)d_in[3];
    const float* wk = (const float*)d_in[4];
    const float* bk = (const float*)d_in[5];
    const float* wv = (const float*)d_in[6];
    const float* bv = (const float*)d_in[7];
    const float* wo = (const float*)d_in[8];
    const float* bo = (const float*)d_in[9];
    float* out = (float*)d_out;

    __half *xh, *xl, *qh, *ql, *ks, *vs, *aoh, *wt;
    cudaGetSymbolAddress((void**)&xh,  g_Xh);
    cudaGetSymbolAddress((void**)&xl,  g_Xl);
    cudaGetSymbolAddress((void**)&qh,  g_Qh);
    cudaGetSymbolAddress((void**)&ql,  g_Ql);
    cudaGetSymbolAddress((void**)&ks,  g_Ks);
    cudaGetSymbolAddress((void**)&vs,  g_Vs);
    cudaGetSymbolAddress((void**)&aoh, g_AOh);
    cudaGetSymbolAddress((void**)&wt,  g_Wt);
    const size_t WSZ = (size_t)Hh * Hh;

    static bool attr_set = false;
    if (!attr_set) {
        cudaFuncSetAttribute(gemm_mma<1, 1>,
                             cudaFuncAttributeMaxDynamicSharedMemorySize, GEMM_SMEM_SPLIT);
        cudaFuncSetAttribute(gemm_mma<2, 1>,
                             cudaFuncAttributeMaxDynamicSharedMemorySize, GEMM_SMEM_SPLIT);
        cudaFuncSetAttribute(gemm_mma<2, 0>,
                             cudaFuncAttributeMaxDynamicSharedMemorySize, GEMM_SMEM_SINGLE);
        cudaFuncSetAttribute(gemm_mma<0, 0>,
                             cudaFuncAttributeMaxDynamicSharedMemorySize, GEMM_SMEM_SINGLE);
        cudaFuncSetAttribute(attn_mma,
                             cudaFuncAttributeMaxDynamicSharedMemorySize, ATT2_SMEM);
        attr_set = true;
    }

    const int N2 = Mm * Hh / 2;
    convert_split<<<(N2 + 255) / 256, 256>>>(
        (const float2*)x, (__half2*)xh, (__half2*)xl, N2);

    transpose_convert4<<<dim3(Hh / 32, Hh / 32, 4), dim3(32, 8)>>>(
        wq, wk, wv, wo, wt);

    dim3 gg(Hh / 128, Mm / 128);
    // Q: x split (exp-amplified path), hi/lo out
    gemm_mma<1, 1><<<gg, 256, GEMM_SMEM_SPLIT>>>(xh, xl, wt + 0 * WSZ, bq,
                                                 nullptr, qh, ql);
    // K: x split (exp-amplified path), single out
    gemm_mma<2, 1><<<gg, 256, GEMM_SMEM_SPLIT>>>(xh, xl, wt + 1 * WSZ, bk,
                                                 nullptr, ks, nullptr);
    // V: x single (linear path), single out
    gemm_mma<2, 0><<<gg, 256, GEMM_SMEM_SINGLE>>>(xh, nullptr, wt + 2 * WSZ, bv,
                                                  nullptr, vs, nullptr);

    attn_mma<<<dim3(Ss / AQT, NHh, Bb), 256, ATT2_SMEM>>>(qh, ql, ks, vs, aoh);

    // Output projection: AO single (linear path), fp32 out
    gemm_mma<0, 0><<<gg, 256, GEMM_SMEM_SINGLE>>>(aoh, nullptr, wt + 3 * WSZ, bo,
                                                  out, nullptr, nullptr);
}

// round 8
// speedup vs baseline: 5.4907x; 1.0480x over previous
#include <cuda_runtime.h>
#include <cuda_fp16.h>
#include <cstdint>

// Problem constants
#define Bb   2
#define Ss   2048
#define Hh   2048
#define NHh  16
#define HDd  128
#define Mm   4096   // B*S

// ---------------------------------------------------------------------------
// Scratch (device globals; no allocation allowed)
// ---------------------------------------------------------------------------
__device__ __half g_Xh[(size_t)Mm * Hh];
__device__ __half g_Xl[(size_t)Mm * Hh];
__device__ __half g_Qh[(size_t)Mm * Hh];
__device__ __half g_Ql[(size_t)Mm * Hh];
__device__ __half g_Ks[(size_t)Mm * Hh];
__device__ __half g_Vs[(size_t)Mm * Hh];
__device__ __half g_AOh[(size_t)Mm * Hh];
__device__ __half g_Wt[4][(size_t)Hh * Hh];

// ---------------------------------------------------------------------------
// PTX helpers (sm_80-level only: legal in compute_103 PTX)
// ---------------------------------------------------------------------------
__device__ __forceinline__ uint32_t smem_to_u32(const void* p) {
    uint32_t a;
    asm("{ .reg .u64 t; cvta.to.shared.u64 t, %1; cvt.u32.u64 %0, t; }"
        : "=r"(a) : "l"(p));
    return a;
}
__device__ __forceinline__ void cp16(uint32_t s, const void* g) {
    asm volatile("cp.async.cg.shared.global [%0], [%1], 16;" :: "r"(s), "l"(g));
}
#define CP_COMMIT() asm volatile("cp.async.commit_group;" ::: "memory")
#define CP_WAIT0()  asm volatile("cp.async.wait_group 0;" ::: "memory")
#define CP_WAIT1()  asm volatile("cp.async.wait_group 1;" ::: "memory")

__device__ __forceinline__ void ldm_x4(uint32_t& r0, uint32_t& r1, uint32_t& r2,
                                       uint32_t& r3, uint32_t addr) {
    asm volatile("ldmatrix.sync.aligned.m8n8.x4.shared.b16 {%0,%1,%2,%3}, [%4];"
                 : "=r"(r0), "=r"(r1), "=r"(r2), "=r"(r3) : "r"(addr));
}
__device__ __forceinline__ void ldm_x4t(uint32_t& r0, uint32_t& r1, uint32_t& r2,
                                        uint32_t& r3, uint32_t addr) {
    asm volatile("ldmatrix.sync.aligned.m8n8.x4.trans.shared.b16 {%0,%1,%2,%3}, [%4];"
                 : "=r"(r0), "=r"(r1), "=r"(r2), "=r"(r3) : "r"(addr));
}
__device__ __forceinline__ void ldm_x2(uint32_t& r0, uint32_t& r1, uint32_t addr) {
    asm volatile("ldmatrix.sync.aligned.m8n8.x2.shared.b16 {%0,%1}, [%2];"
                 : "=r"(r0), "=r"(r1) : "r"(addr));
}
__device__ __forceinline__ void mma_f16(float* c, const uint32_t* a, const uint32_t* b) {
    asm volatile("mma.sync.aligned.m16n8k16.row.col.f32.f16.f16.f32 "
                 "{%0,%1,%2,%3}, {%4,%5,%6,%7}, {%8,%9}, {%0,%1,%2,%3};"
                 : "+f"(c[0]), "+f"(c[1]), "+f"(c[2]), "+f"(c[3])
                 : "r"(a[0]), "r"(a[1]), "r"(a[2]), "r"(a[3]), "r"(b[0]), "r"(b[1]));
}

// Fast exp2 on the FMA pipe (deg-5 poly, f in [-0.5,0.5]); rel err ~2.4e-6.
__device__ __forceinline__ float exp2p(float t) {
    t = fmaxf(t, -120.f);
    float fn = t + 12582912.f;
    int   n  = __float_as_int(fn) - 0x4B400000;
    float f  = t - (fn - 12582912.f);
    float p  = 1.3333558146428443e-3f;
    p = fmaf(p, f, 9.6181291076284772e-3f);
    p = fmaf(p, f, 5.5504108664821580e-2f);
    p = fmaf(p, f, 2.4022650695910071e-1f);
    p = fmaf(p, f, 6.9314718055994531e-1f);
    p = fmaf(p, f, 1.0f);
    return p * __int_as_float((n + 127) << 23);
}

__device__ __forceinline__ uint32_t packh(float x, float y) {
    __half2 t = __floats2half2_rn(x, y);
    return *reinterpret_cast<uint32_t*>(&t);
}

// ---------------------------------------------------------------------------
// Conversions
// ---------------------------------------------------------------------------
__global__ void convert_split(const float2* __restrict__ X,
                              __half2* __restrict__ Xh,
                              __half2* __restrict__ Xl, int n2)
{
    int i = blockIdx.x * blockDim.x + threadIdx.x;
    if (i >= n2) return;
    float2 v = X[i];
    __half h0 = __float2half_rn(v.x);
    __half h1 = __float2half_rn(v.y);
    float r0 = v.x - __half2float(h0);
    float r1 = v.y - __half2float(h1);
    Xh[i] = __half2(h0, h1);
    Xl[i] = __half2(__float2half_rn(r0), __float2half_rn(r1));
}

// Fused transpose + convert for all 4 weights (z selects the matrix)
__global__ void transpose_convert4(const float* __restrict__ w0,
                                   const float* __restrict__ w1,
                                   const float* __restrict__ w2,
                                   const float* __restrict__ w3,
                                   __half* __restrict__ T)
{
    __shared__ float t[32][33];
    const float* W = (blockIdx.z == 0) ? w0 : (blockIdx.z == 1) ? w1
                   : (blockIdx.z == 2) ? w2 : w3;
    __half* Td = T + (size_t)blockIdx.z * Hh * Hh;
    const int n0 = blockIdx.x * 32, k0 = blockIdx.y * 32;
    const int tx = threadIdx.x, ty = threadIdx.y;   // (32, 8)
#pragma unroll
    for (int i = 0; i < 4; i++)
        t[ty + 8 * i][tx] = W[(size_t)(k0 + ty + 8 * i) * Hh + n0 + tx];
    __syncthreads();
#pragma unroll
    for (int i = 0; i < 4; i++)
        Td[(size_t)(n0 + ty + 8 * i) * Hh + k0 + tx] =
            __float2half_rn(t[tx][ty + 8 * i]);
}

// ---------------------------------------------------------------------------
// GEMM common geometry
// ---------------------------------------------------------------------------
#define BKg   32
#define PADR  40
#define TILE_HALFS (128 * PADR)
#define TILE_B ((uint32_t)(TILE_HALFS * 2))
#define QKV_STAGE_B (3u * TILE_B)
#define QKV_SMEM (3 * 3 * (int)TILE_B)

__device__ __forceinline__ void stage_load_rt(uint32_t sb, bool asplit,
    const __half* __restrict__ Ah, const __half* __restrict__ Al,
    const __half* __restrict__ Bs, int bm, int bn, int k0, int tid)
{
    const int r = tid >> 1;
    const int c = (tid & 1) * 2;
#pragma unroll
    for (int cc = 0; cc < 2; cc++) {
        const uint32_t so = (uint32_t)(r * PADR + (c + cc) * 8) * 2;
        const size_t go = (size_t)k0 + (c + cc) * 8;
        cp16(sb + so, Ah + (size_t)(bm + r) * Hh + go);
        if (asplit)
            cp16(sb + TILE_B + so, Al + (size_t)(bm + r) * Hh + go);
        cp16(sb + 2 * TILE_B + so, Bs + (size_t)(bn + r) * Hh + go);
    }
}

// ---------------------------------------------------------------------------
// Merged QKV GEMM: z = 0 (Q: A split, hi/lo out), 1 (K: A split, single out),
// 2 (V: A single, single out). CTA 128x128, BK=32, 3-stage, 2 CTAs/SM.
// ---------------------------------------------------------------------------
__global__ __launch_bounds__(256, 2)
void qkv_mma(const __half* __restrict__ Xh, const __half* __restrict__ Xl,
             const __half* __restrict__ Wt,
             const float* __restrict__ bq, const float* __restrict__ bk,
             const float* __restrict__ bv,
             __half* __restrict__ Qh, __half* __restrict__ Ql,
             __half* __restrict__ Ks, __half* __restrict__ Vs)
{
    extern __shared__ __half smem[];
    const uint32_t sbase = smem_to_u32(smem);
    const int tid = threadIdx.x;
    const int wid = tid >> 5, lane = tid & 31;
    const int z = blockIdx.z;
    const bool asplit = (z < 2);
    const __half* Bs = Wt + (size_t)z * Hh * Hh;
    const float* bias = (z == 0) ? bq : (z == 1) ? bk : bv;
    const int bn = blockIdx.x * 128, bm = blockIdx.y * 128;
    const int wm = (wid >> 2) * 64;
    const int wn = (wid & 3) * 32;

    float acc[4][4][4];
#pragma unroll
    for (int i = 0; i < 4; i++)
#pragma unroll
        for (int j = 0; j < 4; j++)
#pragma unroll
            for (int q = 0; q < 4; q++) acc[i][j][q] = 0.f;

    const int NIT = Hh / BKg;   // 64
    stage_load_rt(sbase, asplit, Xh, Xl, Bs, bm, bn, 0, tid);
    CP_COMMIT();
    stage_load_rt(sbase + QKV_STAGE_B, asplit, Xh, Xl, Bs, bm, bn, BKg, tid);
    CP_COMMIT();
    CP_WAIT1();
    __syncthreads();

    const int arow = lane & 15;
    const int acol8 = (lane >> 4) << 3;
    const int brow = lane & 7;
    const int bcol8 = ((lane >> 3) & 1) << 3;

    for (int kt = 0; kt < NIT; kt++) {
        const uint32_t sb = sbase + (uint32_t)(kt % 3) * QKV_STAGE_B;
        if (kt + 2 < NIT) {
            stage_load_rt(sbase + (uint32_t)((kt + 2) % 3) * QKV_STAGE_B,
                          asplit, Xh, Xl, Bs, bm, bn, (kt + 2) * BKg, tid);
            CP_COMMIT();
        }

#pragma unroll
        for (int ks = 0; ks < 2; ks++) {
            const int k0 = ks * 16;
            uint32_t bF[4][2];
#pragma unroll
            for (int ni = 0; ni < 4; ni++) {
                const uint32_t off =
                    (uint32_t)((wn + ni * 8 + brow) * PADR + k0 + bcol8) * 2;
                ldm_x2(bF[ni][0], bF[ni][1], sb + 2 * TILE_B + off);
            }
#pragma unroll
            for (int mi = 0; mi < 4; mi++) {
                const uint32_t off =
                    (uint32_t)((wm + mi * 16 + arow) * PADR + k0 + acol8) * 2;
                uint32_t aH[4];
                ldm_x4(aH[0], aH[1], aH[2], aH[3], sb + off);
#pragma unroll
                for (int ni = 0; ni < 4; ni++)
                    mma_f16(acc[mi][ni], aH, bF[ni]);
                if (asplit) {
                    uint32_t aL[4];
                    ldm_x4(aL[0], aL[1], aL[2], aL[3], sb + TILE_B + off);
#pragma unroll
                    for (int ni = 0; ni < 4; ni++)
                        mma_f16(acc[mi][ni], aL, bF[ni]);
                }
            }
        }

        if (kt + 1 < NIT) {
            if (kt + 2 < NIT) { CP_WAIT1(); } else { CP_WAIT0(); }
        }
        __syncthreads();
    }

    const int fr = lane >> 2;
    const int fc = (lane & 3) * 2;
#pragma unroll
    for (int mi = 0; mi < 4; mi++) {
#pragma unroll
        for (int ni = 0; ni < 4; ni++) {
            const int n0 = bn + wn + ni * 8 + fc;
            const float b0 = bias[n0], b1 = bias[n0 + 1];
#pragma unroll
            for (int half = 0; half < 2; half++) {
                const int m = bm + wm + mi * 16 + fr + half * 8;
                float v0 = acc[mi][ni][half * 2 + 0] + b0;
                float v1 = acc[mi][ni][half * 2 + 1] + b1;
                const int bb = m >> 11;
                const int ss = m & (Ss - 1);
                const int hh = n0 >> 7;
                const int dd = n0 & (HDd - 1);
                const size_t idx =
                    (((size_t)(bb * NHh + hh) * Ss) + ss) * HDd + dd;
                if (z == 0) {
                    __half h0 = __float2half_rn(v0);
                    __half h1 = __float2half_rn(v1);
                    float r0 = v0 - __half2float(h0);
                    float r1 = v1 - __half2float(h1);
                    *(__half2*)&Qh[idx] = __half2(h0, h1);
                    *(__half2*)&Ql[idx] = __half2(
                        __float2half_rn(r0), __float2half_rn(r1));
                } else if (z == 1) {
                    *(__half2*)&Ks[idx] = __floats2half2_rn(v0, v1);
                } else {
                    *(__half2*)&Vs[idx] = __floats2half2_rn(v0, v1);
                }
            }
        }
    }
}

// ---------------------------------------------------------------------------
// Output projection GEMM: C[M,N] = A @ B^T + bias, fp32 out, single-A.
// ---------------------------------------------------------------------------
#define PROJ_STAGE_B (2u * TILE_B)
#define PROJ_SMEM (3 * 2 * (int)TILE_B)

__global__ __launch_bounds__(256, 2)
void proj_mma(const __half* __restrict__ Ah, const __half* __restrict__ Bw,
              const float* __restrict__ bias, float* __restrict__ Cf)
{
    extern __shared__ __half smem[];
    const uint32_t sbase = smem_to_u32(smem);
    const int tid = threadIdx.x;
    const int wid = tid >> 5, lane = tid & 31;
    const int bn = blockIdx.x * 128, bm = blockIdx.y * 128;
    const int wm = (wid >> 2) * 64;
    const int wn = (wid & 3) * 32;

    float acc[4][4][4];
#pragma unroll
    for (int i = 0; i < 4; i++)
#pragma unroll
        for (int j = 0; j < 4; j++)
#pragma unroll
            for (int q = 0; q < 4; q++) acc[i][j][q] = 0.f;

    const int NIT = Hh / BKg;
    stage_load_rt(sbase, false, Ah, nullptr, Bw, bm, bn, 0, tid);
    CP_COMMIT();
    stage_load_rt(sbase + QKV_STAGE_B, false, Ah, nullptr, Bw, bm, bn, BKg, tid);
    CP_COMMIT();
    CP_WAIT1();
    __syncthreads();

    const int arow = lane & 15;
    const int acol8 = (lane >> 4) << 3;
    const int brow = lane & 7;
    const int bcol8 = ((lane >> 3) & 1) << 3;

    for (int kt = 0; kt < NIT; kt++) {
        const uint32_t sb = sbase + (uint32_t)(kt % 3) * QKV_STAGE_B;
        if (kt + 2 < NIT) {
            stage_load_rt(sbase + (uint32_t)((kt + 2) % 3) * QKV_STAGE_B,
                          false, Ah, nullptr, Bw, bm, bn, (kt + 2) * BKg, tid);
            CP_COMMIT();
        }
#pragma unroll
        for (int ks = 0; ks < 2; ks++) {
            const int k0 = ks * 16;
            uint32_t bF[4][2];
#pragma unroll
            for (int ni = 0; ni < 4; ni++) {
                const uint32_t off =
                    (uint32_t)((wn + ni * 8 + brow) * PADR + k0 + bcol8) * 2;
                ldm_x2(bF[ni][0], bF[ni][1], sb + 2 * TILE_B + off);
            }
#pragma unroll
            for (int mi = 0; mi < 4; mi++) {
                const uint32_t off =
                    (uint32_t)((wm + mi * 16 + arow) * PADR + k0 + acol8) * 2;
                uint32_t aH[4];
                ldm_x4(aH[0], aH[1], aH[2], aH[3], sb + off);
#pragma unroll
                for (int ni = 0; ni < 4; ni++)
                    mma_f16(acc[mi][ni], aH, bF[ni]);
            }
        }
        if (kt + 1 < NIT) {
            if (kt + 2 < NIT) { CP_WAIT1(); } else { CP_WAIT0(); }
        }
        __syncthreads();
    }

    const int fr = lane >> 2;
    const int fc = (lane & 3) * 2;
#pragma unroll
    for (int mi = 0; mi < 4; mi++) {
#pragma unroll
        for (int ni = 0; ni < 4; ni++) {
            const int n0 = bn + wn + ni * 8 + fc;
            const float b0 = bias[n0], b1 = bias[n0 + 1];
#pragma unroll
            for (int half = 0; half < 2; half++) {
                const int m = bm + wm + mi * 16 + fr + half * 8;
                float2 w;
                w.x = acc[mi][ni][half * 2 + 0] + b0;
                w.y = acc[mi][ni][half * 2 + 1] + b1;
                *(float2*)&Cf[(size_t)m * Hh + n0] = w;
            }
        }
    }
}

// ---------------------------------------------------------------------------
// HMMA fp16 flash attention v2: AKT=128, Q_lo resident in smem, single sync/kt.
// CTA: 128 q rows, 8 warps x 16 rows. KV double-buffered cp.async.
// ---------------------------------------------------------------------------
#define AQT 128
#define AKT 128
#define PADV 136
#define Q_TILE_B   (AQT * PADV * 2)        // 34816 bytes (hi), same for lo
#define KV_TILE_B  (AKT * PADV * 2)        // 34816 bytes
#define KV_STAGE_B (2 * KV_TILE_B)         // K, V = 69632 bytes
#define ATT_Q_B    (2 * Q_TILE_B)          // 69632 bytes
#define ATT2_SMEM  (ATT_Q_B + 2 * KV_STAGE_B)   // 208896 bytes

__device__ __forceinline__ void stage_kv2(uint32_t dst, size_t base, int kn0,
    const __half* __restrict__ Ks, const __half* __restrict__ Vs, int tid)
{
#pragma unroll
    for (int i = 0; i < 8; i++) {
        const int idx = i * 256 + tid;
        const int row = idx >> 4, ch = idx & 15;
        const uint32_t so = (uint32_t)(row * PADV + ch * 8) * 2;
        const size_t go = base + (size_t)(kn0 + row) * HDd + ch * 8;
        cp16(dst +             so, Ks + go);
        cp16(dst + KV_TILE_B + so, Vs + go);
    }
}

__global__ __launch_bounds__(256, 1)
void attn_mma(const __half* __restrict__ Qh, const __half* __restrict__ Ql,
              const __half* __restrict__ Ks, const __half* __restrict__ Vs,
              __half* __restrict__ AOh)
{
    extern __shared__ __half asmem[];
    const uint32_t sb = smem_to_u32(asmem);
    const uint32_t QH = sb, QL = sb + Q_TILE_B, KV = sb + ATT_Q_B;
    const int tid = threadIdx.x, wid = tid >> 5, lane = tid & 31;
    const int qi = (int)gridDim.x - 1 - (int)blockIdx.x;   // big tiles first
    const int hh = blockIdx.y, bb = blockIdx.z;
    const size_t base = ((size_t)(bb * NHh + hh)) * Ss * HDd;
    const int q0 = qi * AQT;
    const float Cs = 0.12751745210319466f;   // 128^-0.5 * log2(e)

    const int qrow = wid * 16 + (lane & 15);
    const int qc8 = (lane >> 4) << 3;

    // ---- prologue: Q hi+lo to resident smem; KV tile 0 in flight ----
#pragma unroll
    for (int i = 0; i < 8; i++) {
        const int idx = i * 256 + tid;
        const int row = idx >> 4, ch = idx & 15;
        const uint32_t so = (uint32_t)(row * PADV + ch * 8) * 2;
        const size_t go = base + (size_t)(q0 + row) * HDd + ch * 8;
        cp16(QH + so, Qh + go);
        cp16(QL + so, Ql + go);
    }
    CP_COMMIT();
    stage_kv2(KV, base, 0, Ks, Vs, tid);
    CP_COMMIT();
    CP_WAIT1();          // Q ready
    __syncthreads();

    uint32_t qfh[8][4];
#pragma unroll
    for (int kk = 0; kk < 8; kk++)
        ldm_x4(qfh[kk][0], qfh[kk][1], qfh[kk][2], qfh[kk][3],
               QH + (uint32_t)(qrow * PADV + kk * 16 + qc8) * 2);

    float O[16][4];
#pragma unroll
    for (int i = 0; i < 16; i++)
#pragma unroll
        for (int j = 0; j < 4; j++) O[i][j] = 0.f;
    float m0 = -1e30f, m1 = -1e30f, l0 = 0.f, l1 = 0.f;

    const int nkt = qi + 1;
    for (int kt = 0; kt < nkt; kt++) {
        CP_WAIT0();          // KV(kt) resident
        __syncthreads();     // all warps done with KV(kt-1); visibility of KV(kt)
        if (kt + 1 < nkt) {
            stage_kv2(KV + (uint32_t)(((kt + 1) & 1) * KV_STAGE_B), base,
                      (kt + 1) * AKT, Ks, Vs, tid);
            CP_COMMIT();
        }
        const uint32_t cur = KV + (uint32_t)((kt & 1) * KV_STAGE_B);
        const uint32_t KsS = cur, VsS = cur + KV_TILE_B;

        // ---- scores: 16 n-frags over 128 keys ----
        float c[16][4];
#pragma unroll
        for (int i = 0; i < 16; i++)
#pragma unroll
            for (int j = 0; j < 4; j++) c[i][j] = 0.f;

#pragma unroll
        for (int kk = 0; kk < 8; kk++) {
            uint32_t qfl[4];
            ldm_x4(qfl[0], qfl[1], qfl[2], qfl[3],
                   QL + (uint32_t)(qrow * PADV + kk * 16 + qc8) * 2);
            const uint32_t kc = (uint32_t)(kk * 16 + ((lane >> 3) & 1) * 8) * 2;
#pragma unroll
            for (int nfp = 0; nfp < 8; nfp++) {
                const uint32_t nrow =
                    (uint32_t)(nfp * 16 + ((lane >> 4) << 3) + (lane & 7));
                uint32_t h0, h1, h2, h3;
                ldm_x4(h0, h1, h2, h3, KsS + nrow * (PADV * 2) + kc);
                uint32_t bA[2] = {h0, h1}, bB[2] = {h2, h3};
                mma_f16(c[2 * nfp],     qfh[kk], bA);
                mma_f16(c[2 * nfp],     qfl,     bA);
                mma_f16(c[2 * nfp + 1], qfh[kk], bB);
                mma_f16(c[2 * nfp + 1], qfl,     bB);
            }
        }

        // ---- causal mask (only the diagonal tile) ----
        if (kt == nkt - 1) {
            const int row0 = q0 + wid * 16 + (lane >> 2);
            const int col0 = kt * AKT + (lane & 3) * 2;
#pragma unroll
            for (int nf = 0; nf < 16; nf++) {
                const int cb = col0 + nf * 8;
                if (cb     > row0)     c[nf][0] = -1e30f;
                if (cb + 1 > row0)     c[nf][1] = -1e30f;
                if (cb     > row0 + 8) c[nf][2] = -1e30f;
                if (cb + 1 > row0 + 8) c[nf][3] = -1e30f;
            }
        }

        // ---- online softmax ----
        float rm0 = -1e30f, rm1 = -1e30f;
#pragma unroll
        for (int nf = 0; nf < 16; nf++) {
            rm0 = fmaxf(rm0, fmaxf(c[nf][0], c[nf][1]));
            rm1 = fmaxf(rm1, fmaxf(c[nf][2], c[nf][3]));
        }
        rm0 = fmaxf(rm0, __shfl_xor_sync(0xffffffffu, rm0, 1));
        rm0 = fmaxf(rm0, __shfl_xor_sync(0xffffffffu, rm0, 2));
        rm1 = fmaxf(rm1, __shfl_xor_sync(0xffffffffu, rm1, 1));
        rm1 = fmaxf(rm1, __shfl_xor_sync(0xffffffffu, rm1, 2));
        const float mn0 = fmaxf(m0, rm0), mn1 = fmaxf(m1, rm1);
        const float a0 = exp2p((m0 - mn0) * Cs);
        const float a1 = exp2p((m1 - mn1) * Cs);
        m0 = mn0; m1 = mn1;

        float rs0 = 0.f, rs1 = 0.f;
#pragma unroll
        for (int nf = 0; nf < 16; nf++) {
            c[nf][0] = exp2p((c[nf][0] - mn0) * Cs);
            c[nf][1] = exp2p((c[nf][1] - mn0) * Cs);
            c[nf][2] = exp2p((c[nf][2] - mn1) * Cs);
            c[nf][3] = exp2p((c[nf][3] - mn1) * Cs);
            rs0 += c[nf][0] + c[nf][1];
            rs1 += c[nf][2] + c[nf][3];
        }
        rs0 += __shfl_xor_sync(0xffffffffu, rs0, 1);
        rs0 += __shfl_xor_sync(0xffffffffu, rs0, 2);
        rs1 += __shfl_xor_sync(0xffffffffu, rs1, 1);
        rs1 += __shfl_xor_sync(0xffffffffu, rs1, 2);
        l0 = l0 * a0 + rs0;
        l1 = l1 * a1 + rs1;

#pragma unroll
        for (int i = 0; i < 16; i++) {
            O[i][0] *= a0; O[i][1] *= a0; O[i][2] *= a1; O[i][3] *= a1;
        }

        // ---- O += P @ V (P packed on the fly per 16-key group) ----
#pragma unroll
        for (int k2 = 0; k2 < 8; k2++) {
            uint32_t pah[4];
#pragma unroll
            for (int q = 0; q < 4; q++) {
                const int nf = 2 * k2 + (q >> 1);
                const int e  = (q & 1) * 2;
                pah[q] = packh(c[nf][e], c[nf][e + 1]);
            }
            const uint32_t vr =
                (uint32_t)(k2 * 16 + (lane & 7) + ((lane >> 3) & 1) * 8);
#pragma unroll
            for (int nfp = 0; nfp < 8; nfp++) {
                const uint32_t vc = (uint32_t)(nfp * 16 + ((lane >> 4) << 3));
                uint32_t h0, h1, h2, h3;
                ldm_x4t(h0, h1, h2, h3, VsS + (vr * PADV + vc) * 2);
                uint32_t bA[2] = {h0, h1}, bB[2] = {h2, h3};
                mma_f16(O[2 * nfp],     pah, bA);
                mma_f16(O[2 * nfp + 1], pah, bB);
            }
        }
    }

    // ---- epilogue: normalize, write AO single fp16 [B,S,H] ----
    const float inv0 = 1.f / l0, inv1 = 1.f / l1;
    const int srow0 = q0 + wid * 16 + (lane >> 2);
#pragma unroll
    for (int nf = 0; nf < 16; nf++) {
        const int col = hh * HDd + nf * 8 + (lane & 3) * 2;
        const size_t o0 = ((size_t)(bb * Ss) + srow0) * Hh + col;
        const size_t o1 = o0 + (size_t)8 * Hh;
        *(uint32_t*)&AOh[o0] = packh(O[nf][0] * inv0, O[nf][1] * inv0);
        *(uint32_t*)&AOh[o1] = packh(O[nf][2] * inv1, O[nf][3] * inv1);
    }
}

// ---------------------------------------------------------------------------
extern "C" void kernel_launch(void* const* d_in, const int* in_sizes, int n_in,
                              void* d_out, int out_size)
{
    (void)in_sizes; (void)n_in; (void)out_size;
    const float* x  = (const float*)d_in[0];
    const float* wq = (const float*)d_in[2];
    const float* bq = (const float*)d_in[3];
    const float* wk = (const float*)d_in[4];
    const float* bk = (const float*)d_in[5];
    const float* wv = (const float*)d_in[6];
    const float* bv = (const float*)d_in[7];
    const float* wo = (const float*)d_in[8];
    const float* bo = (const float*)d_in[9];
    float* out = (float*)d_out;

    __half *xh, *xl, *qh, *ql, *ks, *vs, *aoh, *wt;
    cudaGetSymbolAddress((void**)&xh,  g_Xh);
    cudaGetSymbolAddress((void**)&xl,  g_Xl);
    cudaGetSymbolAddress((void**)&qh,  g_Qh);
    cudaGetSymbolAddress((void**)&ql,  g_Ql);
    cudaGetSymbolAddress((void**)&ks,  g_Ks);
    cudaGetSymbolAddress((void**)&vs,  g_Vs);
    cudaGetSymbolAddress((void**)&aoh, g_AOh);
    cudaGetSymbolAddress((void**)&wt,  g_Wt);
    const size_t WSZ = (size_t)Hh * Hh;

    static bool attr_set = false;
    if (!attr_set) {
        cudaFuncSetAttribute(qkv_mma,
                             cudaFuncAttributeMaxDynamicSharedMemorySize, QKV_SMEM);
        cudaFuncSetAttribute(proj_mma,
                             cudaFuncAttributeMaxDynamicSharedMemorySize, QKV_SMEM);
        cudaFuncSetAttribute(attn_mma,
                             cudaFuncAttributeMaxDynamicSharedMemorySize, ATT2_SMEM);
        attr_set = true;
    }

    const int N2 = Mm * Hh / 2;
    convert_split<<<(N2 + 255) / 256, 256>>>(
        (const float2*)x, (__half2*)xh, (__half2*)xl, N2);

    transpose_convert4<<<dim3(Hh / 32, Hh / 32, 4), dim3(32, 8)>>>(
        wq, wk, wv, wo, wt);

    // Q, K, V in one launch (z selects path)
    qkv_mma<<<dim3(Hh / 128, Mm / 128, 3), 256, QKV_SMEM>>>(
        xh, xl, wt, bq, bk, bv, qh, ql, ks, vs);

    attn_mma<<<dim3(Ss / AQT, NHh, Bb), 256, ATT2_SMEM>>>(qh, ql, ks, vs, aoh);

    proj_mma<<<dim3(Hh / 128, Mm / 128), 256, QKV_SMEM>>>(
        aoh, wt + 3 * WSZ, bo, out);
}